// round 2
// baseline (speedup 1.0000x reference)
#include <cuda_runtime.h>
#include <cstdint>

#define NB   64
#define LSEQ 1024
#define DIMK 640
#define NIN  256
#define NOUT 1024

// scratch: 0=Qa(scaled), 1=Ka, 2=Qb(scaled), 3=Kb
__device__ float g_proj[4][NB * LSEQ * NIN];
__device__ float g_recip[2 * NB * LSEQ];
__device__ float g_colsum[2 * NB * LSEQ];
__device__ float g_t[2 * NB * DIMK];

__device__ __forceinline__ float f2tf32(float x) {
    uint32_t u;
    asm("cvt.rna.tf32.f32 %0, %1;" : "=r"(u) : "f"(x));
    return __uint_as_float(u);
}

__device__ __forceinline__ void mma_tf32(float c[4], const uint32_t a[4],
                                         uint32_t b0, uint32_t b1) {
    asm volatile(
        "mma.sync.aligned.m16n8k8.row.col.f32.tf32.tf32.f32 "
        "{%0,%1,%2,%3}, {%4,%5,%6,%7}, {%8,%9}, {%0,%1,%2,%3};"
        : "+f"(c[0]), "+f"(c[1]), "+f"(c[2]), "+f"(c[3])
        : "r"(a[0]), "r"(a[1]), "r"(a[2]), "r"(a[3]), "r"(b0), "r"(b1));
}

__global__ __launch_bounds__(256) void init_kernel() {
    int i = blockIdx.x * 256 + threadIdx.x;
    if (i < 2 * NB * LSEQ) g_colsum[i] = 0.f;
}

// C[65536,256] = X[65536,640] @ W[640,256]; epilogue (acc+bias)*scl.
// Tile 128x128, 8 warps (4m x 2n). Skips row-blocks past len[batch].
__global__ __launch_bounds__(256) void proj_kernel(
    const float* __restrict__ a_pad, const float* __restrict__ b_pad,
    const float* __restrict__ Wq, const float* __restrict__ bq,
    const float* __restrict__ Wk, const float* __restrict__ bk,
    const int* __restrict__ len_a, const int* __restrict__ len_b) {
    __shared__ float As[128 * 36];
    __shared__ float Bs[32 * 136];

    int z = blockIdx.z;
    int m0 = blockIdx.x * 128;
    int batch = m0 >> 10, local = m0 & 1023;
    int len = ((z < 2) ? len_a : len_b)[batch];
    if (local >= len) return;

    const float* X    = (z < 2) ? a_pad : b_pad;
    const float* W    = (z & 1) ? Wk : Wq;
    const float* bias = (z & 1) ? bk : bq;
    float scl         = (z & 1) ? 1.0f : 0.0625f;
    float* dst        = g_proj[z];

    int n0 = blockIdx.y * 128;
    int tid = threadIdx.x;
    int w = tid >> 5, lane = tid & 31;
    int wm = w & 3, wn = w >> 2;
    int g = lane >> 2, t4 = lane & 3;

    int ar[4], ac[4], br[4], bc[4];
#pragma unroll
    for (int i = 0; i < 4; i++) {
        int idx = tid + 256 * i;
        ar[i] = idx >> 3;  ac[i] = (idx & 7) * 4;
        br[i] = idx >> 5;  bc[i] = (idx & 31) * 4;
    }

    float acc[2][8][4] = {};
    float4 pa[4], pb[4];
#pragma unroll
    for (int i = 0; i < 4; i++) {
        pa[i] = *(const float4*)(X + (size_t)(m0 + ar[i]) * DIMK + ac[i]);
        pb[i] = *(const float4*)(W + (size_t)br[i] * NIN + n0 + bc[i]);
    }

    const int NC = DIMK / 32;
    for (int dc = 0; dc < NC; dc++) {
        __syncthreads();
#pragma unroll
        for (int i = 0; i < 4; i++) {
            float* p = As + ar[i] * 36 + ac[i];
            p[0] = f2tf32(pa[i].x); p[1] = f2tf32(pa[i].y);
            p[2] = f2tf32(pa[i].z); p[3] = f2tf32(pa[i].w);
            float* q = Bs + br[i] * 136 + bc[i];
            q[0] = f2tf32(pb[i].x); q[1] = f2tf32(pb[i].y);
            q[2] = f2tf32(pb[i].z); q[3] = f2tf32(pb[i].w);
        }
        __syncthreads();
        if (dc + 1 < NC) {
#pragma unroll
            for (int i = 0; i < 4; i++) {
                pa[i] = *(const float4*)(X + (size_t)(m0 + ar[i]) * DIMK + (dc + 1) * 32 + ac[i]);
                pb[i] = *(const float4*)(W + (size_t)((dc + 1) * 32 + br[i]) * NIN + n0 + bc[i]);
            }
        }
#pragma unroll
        for (int ks = 0; ks < 4; ks++) {
            int kb = ks * 8;
            uint32_t af[2][4];
#pragma unroll
            for (int i = 0; i < 2; i++) {
                int r = wm * 32 + i * 16 + g;
                af[i][0] = __float_as_uint(As[r * 36 + kb + t4]);
                af[i][1] = __float_as_uint(As[(r + 8) * 36 + kb + t4]);
                af[i][2] = __float_as_uint(As[r * 36 + kb + t4 + 4]);
                af[i][3] = __float_as_uint(As[(r + 8) * 36 + kb + t4 + 4]);
            }
#pragma unroll
            for (int j = 0; j < 8; j++) {
                int cb = wn * 64 + j * 8 + g;
                uint32_t b0 = __float_as_uint(Bs[(kb + t4) * 136 + cb]);
                uint32_t b1 = __float_as_uint(Bs[(kb + t4 + 4) * 136 + cb]);
                mma_tf32(acc[0][j], af[0], b0, b1);
                mma_tf32(acc[1][j], af[1], b0, b1);
            }
        }
    }
#pragma unroll
    for (int i = 0; i < 2; i++) {
        int r = m0 + wm * 32 + i * 16 + g;
#pragma unroll
        for (int j = 0; j < 8; j++) {
            int c = n0 + wn * 64 + j * 8 + t4 * 2;
            float bb0 = bias[c], bb1 = bias[c + 1];
            dst[(size_t)r * NIN + c]           = (acc[i][j][0] + bb0) * scl;
            dst[(size_t)r * NIN + c + 1]       = (acc[i][j][1] + bb1) * scl;
            dst[(size_t)(r + 8) * NIN + c]     = (acc[i][j][2] + bb0) * scl;
            dst[(size_t)(r + 8) * NIN + c + 1] = (acc[i][j][3] + bb1) * scl;
        }
    }
}

// pass 0: g_recip = 1 / (rowsum of exp(S));  pass 1: g_colsum += exp(S)^T @ recip
// Grid (qblock=8, batch=64, side=2), 256 threads; 128 q-rows per CTA.
__global__ __launch_bounds__(256) void attn_pass_kernel(
    const int* __restrict__ len_a, const int* __restrict__ len_b, int pass) {
    __shared__ float Qs[128 * 36];
    __shared__ float Ks[128 * 36];
    __shared__ float srow[128];
    __shared__ float scol[1024];

    int side = blockIdx.z, batch = blockIdx.y, q0 = blockIdx.x * 128;
    int len_q = (side == 0) ? len_a[batch] : len_b[batch];
    int len_k = (side == 0) ? len_b[batch] : len_a[batch];
    if (q0 >= len_q) return;

    const float* Qg = g_proj[side == 0 ? 0 : 2] + (size_t)batch * LSEQ * NIN;
    const float* Kg = g_proj[side == 0 ? 3 : 1] + (size_t)batch * LSEQ * NIN;

    int tid = threadIdx.x;
    int w = tid >> 5, lane = tid & 31;
    int wm = w & 3, wn = w >> 2;
    int g = lane >> 2, t4 = lane & 3;

    int lr[4], lc[4];
#pragma unroll
    for (int i = 0; i < 4; i++) {
        int idx = tid + 256 * i;
        lr[i] = idx >> 3;  lc[i] = (idx & 7) * 4;
    }

    if (tid < 128)
        srow[tid] = (pass == 0) ? 0.f
                  : g_recip[side * NB * LSEQ + batch * LSEQ + q0 + tid];
    if (pass == 1)
        for (int i = tid; i < 1024; i += 256) scol[i] = 0.f;

    int nkt = (len_k + 127) >> 7;
    for (int kt = 0; kt < nkt; kt++) {
        int k0 = kt * 128;
        float acc[2][8][4] = {};
        float4 pq[4], pk[4];
#pragma unroll
        for (int i = 0; i < 4; i++) {
            pq[i] = *(const float4*)(Qg + (size_t)(q0 + lr[i]) * NIN + lc[i]);
            pk[i] = *(const float4*)(Kg + (size_t)(k0 + lr[i]) * NIN + lc[i]);
        }
        for (int dc = 0; dc < 8; dc++) {
            __syncthreads();
#pragma unroll
            for (int i = 0; i < 4; i++) {
                float* p = Qs + lr[i] * 36 + lc[i];
                p[0] = f2tf32(pq[i].x); p[1] = f2tf32(pq[i].y);
                p[2] = f2tf32(pq[i].z); p[3] = f2tf32(pq[i].w);
                float* q = Ks + lr[i] * 36 + lc[i];
                q[0] = f2tf32(pk[i].x); q[1] = f2tf32(pk[i].y);
                q[2] = f2tf32(pk[i].z); q[3] = f2tf32(pk[i].w);
            }
            __syncthreads();
            if (dc < 7) {
#pragma unroll
                for (int i = 0; i < 4; i++) {
                    pq[i] = *(const float4*)(Qg + (size_t)(q0 + lr[i]) * NIN + (dc + 1) * 32 + lc[i]);
                    pk[i] = *(const float4*)(Kg + (size_t)(k0 + lr[i]) * NIN + (dc + 1) * 32 + lc[i]);
                }
            }
#pragma unroll
            for (int ks = 0; ks < 4; ks++) {
                int kb = ks * 8;
                uint32_t af[2][4];
#pragma unroll
                for (int i = 0; i < 2; i++) {
                    int r = wm * 32 + i * 16 + g;
                    af[i][0] = __float_as_uint(Qs[r * 36 + kb + t4]);
                    af[i][1] = __float_as_uint(Qs[(r + 8) * 36 + kb + t4]);
                    af[i][2] = __float_as_uint(Qs[r * 36 + kb + t4 + 4]);
                    af[i][3] = __float_as_uint(Qs[(r + 8) * 36 + kb + t4 + 4]);
                }
#pragma unroll
                for (int j = 0; j < 8; j++) {
                    int cb = wn * 64 + j * 8 + g;
                    uint32_t b0 = __float_as_uint(Ks[cb * 36 + kb + t4]);
                    uint32_t b1 = __float_as_uint(Ks[cb * 36 + kb + t4 + 4]);
                    mma_tf32(acc[0][j], af[0], b0, b1);
                    mma_tf32(acc[1][j], af[1], b0, b1);
                }
            }
        }

        if (pass == 0) {
#pragma unroll
            for (int i = 0; i < 2; i++) {
                float rs0 = 0.f, rs1 = 0.f;
#pragma unroll
                for (int j = 0; j < 8; j++) {
                    int kc = k0 + wn * 64 + j * 8 + t4 * 2;
                    if (kc < len_k)     { rs0 += __expf(acc[i][j][0]); rs1 += __expf(acc[i][j][2]); }
                    if (kc + 1 < len_k) { rs0 += __expf(acc[i][j][1]); rs1 += __expf(acc[i][j][3]); }
                }
                rs0 += __shfl_xor_sync(~0u, rs0, 1); rs0 += __shfl_xor_sync(~0u, rs0, 2);
                rs1 += __shfl_xor_sync(~0u, rs1, 1); rs1 += __shfl_xor_sync(~0u, rs1, 2);
                if (t4 == 0) {
                    atomicAdd(&srow[wm * 32 + i * 16 + g], rs0);
                    atomicAdd(&srow[wm * 32 + i * 16 + g + 8], rs1);
                }
            }
        } else {
#pragma unroll
            for (int j = 0; j < 8; j++) {
                int kc = k0 + wn * 64 + j * 8 + t4 * 2;
                float v0 = 0.f, v1 = 0.f;
#pragma unroll
                for (int i = 0; i < 2; i++) {
                    int rl = wm * 32 + i * 16 + g;
                    float w0 = (q0 + rl < len_q) ? srow[rl] : 0.f;
                    float w8 = (q0 + rl + 8 < len_q) ? srow[rl + 8] : 0.f;
                    if (kc < len_k)
                        v0 += __expf(acc[i][j][0]) * w0 + __expf(acc[i][j][2]) * w8;
                    if (kc + 1 < len_k)
                        v1 += __expf(acc[i][j][1]) * w0 + __expf(acc[i][j][3]) * w8;
                }
#pragma unroll
                for (int s = 4; s < 32; s <<= 1) {
                    v0 += __shfl_xor_sync(~0u, v0, s);
                    v1 += __shfl_xor_sync(~0u, v1, s);
                }
                if (g == 0) {
                    atomicAdd(&scol[kc], v0);
                    atomicAdd(&scol[kc + 1], v1);
                }
            }
        }
    }
    __syncthreads();
    if (pass == 0) {
        if (tid < 128)
            g_recip[side * NB * LSEQ + batch * LSEQ + q0 + tid] = 1.0f / srow[tid];
    } else {
        float* dst = g_colsum + side * NB * LSEQ + batch * LSEQ;
        for (int i = tid; i < 1024; i += 256)
            if (scol[i] != 0.f) atomicAdd(&dst[i], scol[i]);
    }
}

// t[side,batch,:] = colsum @ pad   (rank-1 reduction over valid keys)
__global__ __launch_bounds__(256) void tvec_kernel(
    const float* __restrict__ a_pad, const float* __restrict__ b_pad,
    const int* __restrict__ len_a, const int* __restrict__ len_b) {
    int sb = blockIdx.x, side = sb >> 6, batch = sb & 63;
    int lk = ((side == 0) ? len_b : len_a)[batch];
    const float* pad = ((side == 0) ? b_pad : a_pad) + (size_t)batch * LSEQ * DIMK;
    const float* cs = g_colsum + side * NB * LSEQ + batch * LSEQ;
    int d0 = threadIdx.x;
    float a0 = 0.f, a1 = 0.f, a2 = 0.f;
    for (int k = 0; k < lk; k++) {
        float c = cs[k];
        const float* row = pad + (size_t)k * DIMK;
        a0 += c * row[d0];
        a1 += c * row[d0 + 256];
        if (d0 < 128) a2 += c * row[d0 + 512];
    }
    float* t = g_t + (size_t)sb * DIMK;
    t[d0] = a0; t[d0 + 256] = a1;
    if (d0 < 128) t[d0 + 512] = a2;
}

// out[side,batch,:] = t @ Wv / len + bv
__global__ __launch_bounds__(256) void emb_kernel(
    const float* __restrict__ Wv, const float* __restrict__ bv,
    const int* __restrict__ len_a, const int* __restrict__ len_b,
    float* __restrict__ out) {
    int sb = blockIdx.x, side = sb >> 6, batch = sb & 63;
    __shared__ float ts[DIMK];
    for (int i = threadIdx.x; i < DIMK; i += 256) ts[i] = g_t[(size_t)sb * DIMK + i];
    __syncthreads();
    float inv = 1.0f / (float)(((side == 0) ? len_a : len_b)[batch]);
    float acc[4] = {0.f, 0.f, 0.f, 0.f};
    int o = threadIdx.x;
    for (int d = 0; d < DIMK; d++) {
        float tv = ts[d];
        const float* wr = Wv + (size_t)d * NOUT + o;
        acc[0] += tv * wr[0];   acc[1] += tv * wr[256];
        acc[2] += tv * wr[512]; acc[3] += tv * wr[768];
    }
#pragma unroll
    for (int j = 0; j < 4; j++)
        out[(size_t)sb * NOUT + o + j * 256] = acc[j] * inv + bv[o + j * 256];
}

extern "C" void kernel_launch(void* const* d_in, const int* in_sizes, int n_in,
                              void* d_out, int out_size) {
    const float* a_pad = (const float*)d_in[0];
    const float* b_pad = (const float*)d_in[1];
    const int*   len_a = (const int*)d_in[2];
    const int*   len_b = (const int*)d_in[3];
    const float* Wq = (const float*)d_in[4];
    const float* bq = (const float*)d_in[5];
    const float* Wk = (const float*)d_in[6];
    const float* bk = (const float*)d_in[7];
    const float* Wv = (const float*)d_in[8];
    const float* bv = (const float*)d_in[9];
    float* out = (float*)d_out;

    init_kernel<<<(2 * NB * LSEQ + 255) / 256, 256>>>();
    dim3 gp(NB * LSEQ / 128, NIN / 128, 4);
    proj_kernel<<<gp, 256>>>(a_pad, b_pad, Wq, bq, Wk, bk, len_a, len_b);
    dim3 ga(LSEQ / 128, NB, 2);
    attn_pass_kernel<<<ga, 256>>>(len_a, len_b, 0);
    attn_pass_kernel<<<ga, 256>>>(len_a, len_b, 1);
    tvec_kernel<<<2 * NB, 256>>>(a_pad, b_pad, len_a, len_b);
    emb_kernel<<<2 * NB, 256>>>(Wv, bv, len_a, len_b, out);
}

// round 3
// speedup vs baseline: 1.2478x; 1.2478x over previous
#include <cuda_runtime.h>
#include <cstdint>

#define NB   64
#define LSEQ 1024
#define DIMK 640
#define NIN  256
#define NOUT 1024

// scratch: 0=Qa(scaled), 1=Ka, 2=Qb(scaled), 3=Kb
__device__ float g_proj[4][NB * LSEQ * NIN];          // 256 MB
__device__ float g_exp[2ull * NB * LSEQ * LSEQ];      // 512 MB
__device__ float g_recip[2 * NB * LSEQ];
__device__ float g_colsum[2 * NB * LSEQ];
__device__ float g_t[2 * NB * DIMK];

__device__ __forceinline__ float f2tf32(float x) {
    uint32_t u;
    asm("cvt.rna.tf32.f32 %0, %1;" : "=r"(u) : "f"(x));
    return __uint_as_float(u);
}

__device__ __forceinline__ void mma_tf32(float c[4], const uint32_t a[4],
                                         uint32_t b0, uint32_t b1) {
    asm volatile(
        "mma.sync.aligned.m16n8k8.row.col.f32.tf32.tf32.f32 "
        "{%0,%1,%2,%3}, {%4,%5,%6,%7}, {%8,%9}, {%0,%1,%2,%3};"
        : "+f"(c[0]), "+f"(c[1]), "+f"(c[2]), "+f"(c[3])
        : "r"(a[0]), "r"(a[1]), "r"(a[2]), "r"(a[3]), "r"(b0), "r"(b1));
}

__global__ __launch_bounds__(256) void init_kernel() {
    int i = blockIdx.x * 256 + threadIdx.x;
    if (i < 2 * NB * DIMK) g_t[i] = 0.f;
}

// ---------------------------------------------------------------------------
// Projection: C[65536,256] = X[65536,640] @ W[640,256]; (acc+bias)*scl.
// CTA tile 128x256, 8 warps 2m x 4n (warp 64x64). K-chunk 16, double-buffered.
// Dynamic smem: As[2][128][20] + Bs[2][16][264] = 54272 B.
// ---------------------------------------------------------------------------
__global__ __launch_bounds__(256) void proj_kernel(
    const float* __restrict__ a_pad, const float* __restrict__ b_pad,
    const float* __restrict__ Wq, const float* __restrict__ bq,
    const float* __restrict__ Wk, const float* __restrict__ bk,
    const int* __restrict__ len_a, const int* __restrict__ len_b) {
    extern __shared__ float sm[];
    float* As = sm;          // 2*128*20 = 5120 floats
    float* Bs = sm + 5120;   // 2*16*264 = 8448 floats

    int z = blockIdx.z;
    int m0 = blockIdx.x * 128;
    int batch = m0 >> 10, local = m0 & 1023;
    int len = ((z < 2) ? len_a : len_b)[batch];
    if (local >= len) return;

    const float* X    = (z < 2) ? a_pad : b_pad;
    const float* W    = (z & 1) ? Wk : Wq;
    const float* bias = (z & 1) ? bk : bq;
    float scl         = (z & 1) ? 1.0f : 0.0625f;
    float* dst        = g_proj[z];

    int tid = threadIdx.x;
    int w = tid >> 5, lane = tid & 31;
    int wm = w & 1, wn = w >> 1;
    int g = lane >> 2, t4 = lane & 3;

    int ar[2], ac[2], br[4], bc[4];
#pragma unroll
    for (int i = 0; i < 2; i++) {
        int idx = tid + 256 * i;
        ar[i] = idx >> 2;  ac[i] = (idx & 3) * 4;
    }
#pragma unroll
    for (int i = 0; i < 4; i++) {
        int idx = tid + 256 * i;
        br[i] = idx >> 6;  bc[i] = (idx & 63) * 4;
    }

    float acc[4][8][4] = {};
    float4 pa[2], pb[4];

    const int NS = DIMK / 16;  // 40
    // prologue: stage 0
#pragma unroll
    for (int i = 0; i < 2; i++)
        pa[i] = *(const float4*)(X + (size_t)(m0 + ar[i]) * DIMK + ac[i]);
#pragma unroll
    for (int i = 0; i < 4; i++)
        pb[i] = *(const float4*)(W + (size_t)br[i] * NIN + bc[i]);
#pragma unroll
    for (int i = 0; i < 2; i++) {
        float4 v; v.x = f2tf32(pa[i].x); v.y = f2tf32(pa[i].y);
        v.z = f2tf32(pa[i].z); v.w = f2tf32(pa[i].w);
        *(float4*)(As + ar[i] * 20 + ac[i]) = v;
    }
#pragma unroll
    for (int i = 0; i < 4; i++) {
        float4 v; v.x = f2tf32(pb[i].x); v.y = f2tf32(pb[i].y);
        v.z = f2tf32(pb[i].z); v.w = f2tf32(pb[i].w);
        *(float4*)(Bs + br[i] * 264 + bc[i]) = v;
    }
    __syncthreads();

    for (int s = 0; s < NS; s++) {
        int buf = s & 1;
        if (s + 1 < NS) {
#pragma unroll
            for (int i = 0; i < 2; i++)
                pa[i] = *(const float4*)(X + (size_t)(m0 + ar[i]) * DIMK + (s + 1) * 16 + ac[i]);
#pragma unroll
            for (int i = 0; i < 4; i++)
                pb[i] = *(const float4*)(W + (size_t)((s + 1) * 16 + br[i]) * NIN + bc[i]);
        }
        const float* Ab = As + buf * 2560;
        const float* Bb = Bs + buf * 4224;
#pragma unroll
        for (int ks = 0; ks < 2; ks++) {
            int kb = ks * 8;
            uint32_t af[4][4];
#pragma unroll
            for (int i = 0; i < 4; i++) {
                int r = wm * 64 + i * 16 + g;
                af[i][0] = __float_as_uint(Ab[r * 20 + kb + t4]);
                af[i][1] = __float_as_uint(Ab[(r + 8) * 20 + kb + t4]);
                af[i][2] = __float_as_uint(Ab[r * 20 + kb + t4 + 4]);
                af[i][3] = __float_as_uint(Ab[(r + 8) * 20 + kb + t4 + 4]);
            }
#pragma unroll
            for (int j = 0; j < 8; j++) {
                int cb = wn * 64 + j * 8 + g;
                uint32_t b0 = __float_as_uint(Bb[(kb + t4) * 264 + cb]);
                uint32_t b1 = __float_as_uint(Bb[(kb + t4 + 4) * 264 + cb]);
#pragma unroll
                for (int i = 0; i < 4; i++) mma_tf32(acc[i][j], af[i], b0, b1);
            }
        }
        if (s + 1 < NS) {
            int nb = buf ^ 1;
#pragma unroll
            for (int i = 0; i < 2; i++) {
                float4 v; v.x = f2tf32(pa[i].x); v.y = f2tf32(pa[i].y);
                v.z = f2tf32(pa[i].z); v.w = f2tf32(pa[i].w);
                *(float4*)(As + nb * 2560 + ar[i] * 20 + ac[i]) = v;
            }
#pragma unroll
            for (int i = 0; i < 4; i++) {
                float4 v; v.x = f2tf32(pb[i].x); v.y = f2tf32(pb[i].y);
                v.z = f2tf32(pb[i].z); v.w = f2tf32(pb[i].w);
                *(float4*)(Bs + nb * 4224 + br[i] * 264 + bc[i]) = v;
            }
        }
        __syncthreads();
    }

#pragma unroll
    for (int i = 0; i < 4; i++) {
        int r = m0 + wm * 64 + i * 16 + g;
#pragma unroll
        for (int j = 0; j < 8; j++) {
            int c = wn * 64 + j * 8 + t4 * 2;
            float bb0 = bias[c], bb1 = bias[c + 1];
            float2 v0 = make_float2((acc[i][j][0] + bb0) * scl, (acc[i][j][1] + bb1) * scl);
            float2 v1 = make_float2((acc[i][j][2] + bb0) * scl, (acc[i][j][3] + bb1) * scl);
            *(float2*)(dst + (size_t)r * NIN + c) = v0;
            *(float2*)(dst + (size_t)(r + 8) * NIN + c) = v1;
        }
    }
}

// ---------------------------------------------------------------------------
// Attention scores (single pass): S = Q @ K^T, E = exp(S) stored to g_exp,
// row sums -> g_recip. CTA: 128 q x 256 k, 8 warps 2m x 4n, K-chunk 16 DB.
// Dynamic smem: Qs[2][128][20] + Ks[2][256][20] + srow[128] = 61952 B.
// ---------------------------------------------------------------------------
__global__ __launch_bounds__(256) void attn_kernel(
    const int* __restrict__ len_a, const int* __restrict__ len_b) {
    extern __shared__ float sm[];
    float* Qs = sm;             // 5120 floats
    float* Ks = sm + 5120;      // 10240 floats
    float* srow = sm + 15360;   // 128 floats

    int side = blockIdx.z, batch = blockIdx.y, q0 = blockIdx.x * 128;
    int len_q = (side == 0) ? len_a[batch] : len_b[batch];
    int len_k = (side == 0) ? len_b[batch] : len_a[batch];
    if (q0 >= len_q) return;

    const float* Qg = g_proj[side == 0 ? 0 : 2] + (size_t)batch * LSEQ * NIN;
    const float* Kg = g_proj[side == 0 ? 3 : 1] + (size_t)batch * LSEQ * NIN;
    float* Eb = g_exp + (size_t)(side * NB + batch) * LSEQ * LSEQ;

    int tid = threadIdx.x;
    int w = tid >> 5, lane = tid & 31;
    int wm = w & 1, wn = w >> 1;
    int g = lane >> 2, t4 = lane & 3;

    int qr[2], qc[2], kr[4], kc4[4];
#pragma unroll
    for (int i = 0; i < 2; i++) {
        int idx = tid + 256 * i;
        qr[i] = idx >> 2;  qc[i] = (idx & 3) * 4;
    }
#pragma unroll
    for (int i = 0; i < 4; i++) {
        int idx = tid + 256 * i;
        kr[i] = idx >> 2;  kc4[i] = (idx & 3) * 4;
    }

    if (tid < 128) srow[tid] = 0.f;

    int nkt = (len_k + 255) >> 8;
    for (int kt = 0; kt < nkt; kt++) {
        int k0 = kt * 256;
        float acc[4][8][4] = {};
        float4 pq[2], pk[4];
        const int NS = NIN / 16;  // 16
#pragma unroll
        for (int i = 0; i < 2; i++)
            pq[i] = *(const float4*)(Qg + (size_t)(q0 + qr[i]) * NIN + qc[i]);
#pragma unroll
        for (int i = 0; i < 4; i++)
            pk[i] = *(const float4*)(Kg + (size_t)(k0 + kr[i]) * NIN + kc4[i]);
        __syncthreads();  // protect smem reuse across kt / srow init
#pragma unroll
        for (int i = 0; i < 2; i++) {
            float4 v; v.x = f2tf32(pq[i].x); v.y = f2tf32(pq[i].y);
            v.z = f2tf32(pq[i].z); v.w = f2tf32(pq[i].w);
            *(float4*)(Qs + qr[i] * 20 + qc[i]) = v;
        }
#pragma unroll
        for (int i = 0; i < 4; i++) {
            float4 v; v.x = f2tf32(pk[i].x); v.y = f2tf32(pk[i].y);
            v.z = f2tf32(pk[i].z); v.w = f2tf32(pk[i].w);
            *(float4*)(Ks + kr[i] * 20 + kc4[i]) = v;
        }
        __syncthreads();

        for (int s = 0; s < NS; s++) {
            int buf = s & 1;
            if (s + 1 < NS) {
#pragma unroll
                for (int i = 0; i < 2; i++)
                    pq[i] = *(const float4*)(Qg + (size_t)(q0 + qr[i]) * NIN + (s + 1) * 16 + qc[i]);
#pragma unroll
                for (int i = 0; i < 4; i++)
                    pk[i] = *(const float4*)(Kg + (size_t)(k0 + kr[i]) * NIN + (s + 1) * 16 + kc4[i]);
            }
            const float* Qb = Qs + buf * 2560;
            const float* Kb = Ks + buf * 5120;
#pragma unroll
            for (int ks = 0; ks < 2; ks++) {
                int kb = ks * 8;
                uint32_t af[4][4];
#pragma unroll
                for (int i = 0; i < 4; i++) {
                    int r = wm * 64 + i * 16 + g;
                    af[i][0] = __float_as_uint(Qb[r * 20 + kb + t4]);
                    af[i][1] = __float_as_uint(Qb[(r + 8) * 20 + kb + t4]);
                    af[i][2] = __float_as_uint(Qb[r * 20 + kb + t4 + 4]);
                    af[i][3] = __float_as_uint(Qb[(r + 8) * 20 + kb + t4 + 4]);
                }
#pragma unroll
                for (int j = 0; j < 8; j++) {
                    int cb = wn * 64 + j * 8 + g;
                    uint32_t b0 = __float_as_uint(Kb[cb * 20 + kb + t4]);
                    uint32_t b1 = __float_as_uint(Kb[cb * 20 + kb + t4 + 4]);
#pragma unroll
                    for (int i = 0; i < 4; i++) mma_tf32(acc[i][j], af[i], b0, b1);
                }
            }
            if (s + 1 < NS) {
                int nb = buf ^ 1;
#pragma unroll
                for (int i = 0; i < 2; i++) {
                    float4 v; v.x = f2tf32(pq[i].x); v.y = f2tf32(pq[i].y);
                    v.z = f2tf32(pq[i].z); v.w = f2tf32(pq[i].w);
                    *(float4*)(Qs + nb * 2560 + qr[i] * 20 + qc[i]) = v;
                }
#pragma unroll
                for (int i = 0; i < 4; i++) {
                    float4 v; v.x = f2tf32(pk[i].x); v.y = f2tf32(pk[i].y);
                    v.z = f2tf32(pk[i].z); v.w = f2tf32(pk[i].w);
                    *(float4*)(Ks + nb * 5120 + kr[i] * 20 + kc4[i]) = v;
                }
            }
            __syncthreads();
        }

        // epilogue: exp, store E, accumulate row sums
#pragma unroll
        for (int i = 0; i < 4; i++) {
            int r = wm * 64 + i * 16 + g;
            float rs0 = 0.f, rs1 = 0.f;
#pragma unroll
            for (int j = 0; j < 8; j++) {
                int kc = k0 + wn * 64 + j * 8 + t4 * 2;
                float e00 = (kc < len_k) ? __expf(acc[i][j][0]) : 0.f;
                float e01 = (kc + 1 < len_k) ? __expf(acc[i][j][1]) : 0.f;
                float e10 = (kc < len_k) ? __expf(acc[i][j][2]) : 0.f;
                float e11 = (kc + 1 < len_k) ? __expf(acc[i][j][3]) : 0.f;
                *(float2*)(Eb + (size_t)(q0 + r) * LSEQ + kc) = make_float2(e00, e01);
                *(float2*)(Eb + (size_t)(q0 + r + 8) * LSEQ + kc) = make_float2(e10, e11);
                rs0 += e00 + e01;
                rs1 += e10 + e11;
            }
            rs0 += __shfl_xor_sync(~0u, rs0, 1); rs0 += __shfl_xor_sync(~0u, rs0, 2);
            rs1 += __shfl_xor_sync(~0u, rs1, 1); rs1 += __shfl_xor_sync(~0u, rs1, 2);
            if (t4 == 0) {
                atomicAdd(&srow[r], rs0);
                atomicAdd(&srow[r + 8], rs1);
            }
        }
    }
    __syncthreads();
    if (tid < 128)
        g_recip[(side * NB + batch) * LSEQ + q0 + tid] = 1.0f / srow[tid];
}

// colsum_k = sum_q E[q,k] * recip[q]   (memory-bound GEMV per batch/side)
__global__ __launch_bounds__(256) void colsum_kernel(
    const int* __restrict__ len_a, const int* __restrict__ len_b) {
    int side = blockIdx.z, batch = blockIdx.y;
    int len_q = (side == 0) ? len_a[batch] : len_b[batch];
    int len_k = (side == 0) ? len_b[batch] : len_a[batch];
    int k = blockIdx.x * 256 + threadIdx.x;
    if (k >= len_k) return;
    const float* E = g_exp + (size_t)(side * NB + batch) * LSEQ * LSEQ;
    const float* r = g_recip + (side * NB + batch) * LSEQ;
    float acc = 0.f;
    int q = 0;
    for (; q + 4 <= len_q; q += 4)
        acc += E[(size_t)q * LSEQ + k] * r[q]
             + E[(size_t)(q + 1) * LSEQ + k] * r[q + 1]
             + E[(size_t)(q + 2) * LSEQ + k] * r[q + 2]
             + E[(size_t)(q + 3) * LSEQ + k] * r[q + 3];
    for (; q < len_q; q++) acc += E[(size_t)q * LSEQ + k] * r[q];
    g_colsum[(side * NB + batch) * LSEQ + k] = acc;
}

// t[sb,:] += colsum_chunk @ pad   (rank-1 reduction, 4-way k split)
__global__ __launch_bounds__(640) void tvec_kernel(
    const float* __restrict__ a_pad, const float* __restrict__ b_pad,
    const int* __restrict__ len_a, const int* __restrict__ len_b) {
    int sb = blockIdx.y, side = sb >> 6, batch = sb & 63;
    int lk = (side == 0) ? len_b[batch] : len_a[batch];
    int k0 = blockIdx.x * 256;
    if (k0 >= lk) return;
    int k1 = min(k0 + 256, lk);
    const float* pad = ((side == 0) ? b_pad : a_pad) + (size_t)batch * LSEQ * DIMK;
    const float* cs = g_colsum + sb * LSEQ;
    int d = threadIdx.x;
    float acc = 0.f;
    for (int k = k0; k < k1; k++) acc += cs[k] * pad[(size_t)k * DIMK + d];
    atomicAdd(&g_t[sb * DIMK + d], acc);
}

// out[sb,:] = t[sb,:] @ Wv / len + bv   (2 rows per CTA to halve Wv traffic)
__global__ __launch_bounds__(256) void emb_kernel(
    const float* __restrict__ Wv, const float* __restrict__ bv,
    const int* __restrict__ len_a, const int* __restrict__ len_b,
    float* __restrict__ out) {
    int sb0 = blockIdx.x * 2;
    __shared__ float ts[2 * DIMK];
    for (int i = threadIdx.x; i < 2 * DIMK; i += 256) ts[i] = g_t[(size_t)sb0 * DIMK + i];
    __syncthreads();
    int s0 = sb0 >> 6, b0 = sb0 & 63, s1 = (sb0 + 1) >> 6, b1 = (sb0 + 1) & 63;
    float inv0 = 1.0f / (float)((s0 == 0 ? len_a : len_b)[b0]);
    float inv1 = 1.0f / (float)((s1 == 0 ? len_a : len_b)[b1]);
    int o = threadIdx.x;
    float acc[2][4] = {};
    for (int d = 0; d < DIMK; d++) {
        const float* wr = Wv + (size_t)d * NOUT + o;
        float t0 = ts[d], t1 = ts[DIMK + d];
#pragma unroll
        for (int j = 0; j < 4; j++) {
            float wv = wr[j * 256];
            acc[0][j] += t0 * wv;
            acc[1][j] += t1 * wv;
        }
    }
#pragma unroll
    for (int j = 0; j < 4; j++) {
        float bb = bv[o + j * 256];
        out[(size_t)sb0 * NOUT + o + j * 256]       = acc[0][j] * inv0 + bb;
        out[(size_t)(sb0 + 1) * NOUT + o + j * 256] = acc[1][j] * inv1 + bb;
    }
}

extern "C" void kernel_launch(void* const* d_in, const int* in_sizes, int n_in,
                              void* d_out, int out_size) {
    const float* a_pad = (const float*)d_in[0];
    const float* b_pad = (const float*)d_in[1];
    const int*   len_a = (const int*)d_in[2];
    const int*   len_b = (const int*)d_in[3];
    const float* Wq = (const float*)d_in[4];
    const float* bq = (const float*)d_in[5];
    const float* Wk = (const float*)d_in[6];
    const float* bk = (const float*)d_in[7];
    const float* Wv = (const float*)d_in[8];
    const float* bv = (const float*)d_in[9];
    float* out = (float*)d_out;

    cudaFuncSetAttribute(proj_kernel, cudaFuncAttributeMaxDynamicSharedMemorySize, 54272);
    cudaFuncSetAttribute(attn_kernel, cudaFuncAttributeMaxDynamicSharedMemorySize, 61952);

    init_kernel<<<(2 * NB * DIMK + 255) / 256, 256>>>();
    dim3 gp(NB * LSEQ / 128, 1, 4);
    proj_kernel<<<gp, 256, 54272>>>(a_pad, b_pad, Wq, bq, Wk, bk, len_a, len_b);
    dim3 ga(LSEQ / 128, NB, 2);
    attn_kernel<<<ga, 256, 61952>>>(len_a, len_b);
    dim3 gc(4, NB, 2);
    colsum_kernel<<<gc, 256>>>(len_a, len_b);
    dim3 gt(4, 2 * NB);
    tvec_kernel<<<gt, 640>>>(a_pad, b_pad, len_a, len_b);
    emb_kernel<<<NB, 256>>>(Wv, bv, len_a, len_b, out);
}

// round 4
// speedup vs baseline: 1.4644x; 1.1736x over previous
#include <cuda_runtime.h>
#include <cstdint>

#define NB   64
#define LSEQ 1024
#define DIMK 640
#define NIN  256
#define NOUT 1024

// scratch: 0=Qa(scaled), 1=Ka, 2=Qb(scaled), 3=Kb
__device__ float g_proj[4][NB * LSEQ * NIN];          // 256 MB
__device__ float g_exp[2ull * NB * LSEQ * LSEQ];      // 512 MB
__device__ float g_recip[2 * NB * LSEQ];
__device__ float g_colsum[2 * NB * LSEQ];
__device__ float g_t[2 * NB * DIMK];

__device__ __forceinline__ float f2tf32(float x) {
    uint32_t u;
    asm("cvt.rna.tf32.f32 %0, %1;" : "=r"(u) : "f"(x));
    return __uint_as_float(u);
}

__device__ __forceinline__ void mma_tf32(float c[4], const uint32_t a[4],
                                         uint32_t b0, uint32_t b1) {
    asm volatile(
        "mma.sync.aligned.m16n8k8.row.col.f32.tf32.tf32.f32 "
        "{%0,%1,%2,%3}, {%4,%5,%6,%7}, {%8,%9}, {%0,%1,%2,%3};"
        : "+f"(c[0]), "+f"(c[1]), "+f"(c[2]), "+f"(c[3])
        : "r"(a[0]), "r"(a[1]), "r"(a[2]), "r"(a[3]), "r"(b0), "r"(b1));
}

__global__ __launch_bounds__(256) void init_kernel() {
    int i = blockIdx.x * 256 + threadIdx.x;
    if (i < 2 * NB * DIMK) g_t[i] = 0.f;
}

// ---------------------------------------------------------------------------
// Projection: C[65536,256] = X[65536,640] @ W[640,256]; (acc+bias)*scl.
// CTA tile 128x256, 8 warps 2m x 4n (warp 64x64). K-chunk 16, double-buffered.
// ---------------------------------------------------------------------------
__global__ __launch_bounds__(256) void proj_kernel(
    const float* __restrict__ a_pad, const float* __restrict__ b_pad,
    const float* __restrict__ Wq, const float* __restrict__ bq,
    const float* __restrict__ Wk, const float* __restrict__ bk,
    const int* __restrict__ len_a, const int* __restrict__ len_b) {
    extern __shared__ float sm[];
    float* As = sm;          // 2*128*20
    float* Bs = sm + 5120;   // 2*16*264

    int z = blockIdx.z;
    int m0 = blockIdx.x * 128;
    int batch = m0 >> 10, local = m0 & 1023;
    int len = ((z < 2) ? len_a : len_b)[batch];
    if (local >= len) return;

    const float* X    = (z < 2) ? a_pad : b_pad;
    const float* W    = (z & 1) ? Wk : Wq;
    const float* bias = (z & 1) ? bk : bq;
    float scl         = (z & 1) ? 1.0f : 0.0625f;
    float* dst        = g_proj[z];

    int tid = threadIdx.x;
    int w = tid >> 5, lane = tid & 31;
    int wm = w & 1, wn = w >> 1;
    int g = lane >> 2, t4 = lane & 3;

    int ar[2], ac[2], br[4], bc[4];
#pragma unroll
    for (int i = 0; i < 2; i++) {
        int idx = tid + 256 * i;
        ar[i] = idx >> 2;  ac[i] = (idx & 3) * 4;
    }
#pragma unroll
    for (int i = 0; i < 4; i++) {
        int idx = tid + 256 * i;
        br[i] = idx >> 6;  bc[i] = (idx & 63) * 4;
    }

    float acc[4][8][4] = {};
    float4 pa[2], pb[4];

    const int NS = DIMK / 16;  // 40
#pragma unroll
    for (int i = 0; i < 2; i++)
        pa[i] = *(const float4*)(X + (size_t)(m0 + ar[i]) * DIMK + ac[i]);
#pragma unroll
    for (int i = 0; i < 4; i++)
        pb[i] = *(const float4*)(W + (size_t)br[i] * NIN + bc[i]);
#pragma unroll
    for (int i = 0; i < 2; i++) {
        float4 v; v.x = f2tf32(pa[i].x); v.y = f2tf32(pa[i].y);
        v.z = f2tf32(pa[i].z); v.w = f2tf32(pa[i].w);
        *(float4*)(As + ar[i] * 20 + ac[i]) = v;
    }
#pragma unroll
    for (int i = 0; i < 4; i++) {
        float4 v; v.x = f2tf32(pb[i].x); v.y = f2tf32(pb[i].y);
        v.z = f2tf32(pb[i].z); v.w = f2tf32(pb[i].w);
        *(float4*)(Bs + br[i] * 264 + bc[i]) = v;
    }
    __syncthreads();

    for (int s = 0; s < NS; s++) {
        int buf = s & 1;
        if (s + 1 < NS) {
#pragma unroll
            for (int i = 0; i < 2; i++)
                pa[i] = *(const float4*)(X + (size_t)(m0 + ar[i]) * DIMK + (s + 1) * 16 + ac[i]);
#pragma unroll
            for (int i = 0; i < 4; i++)
                pb[i] = *(const float4*)(W + (size_t)((s + 1) * 16 + br[i]) * NIN + bc[i]);
        }
        const float* Ab = As + buf * 2560;
        const float* Bb = Bs + buf * 4224;
#pragma unroll
        for (int ks = 0; ks < 2; ks++) {
            int kb = ks * 8;
            uint32_t af[4][4];
#pragma unroll
            for (int i = 0; i < 4; i++) {
                int r = wm * 64 + i * 16 + g;
                af[i][0] = __float_as_uint(Ab[r * 20 + kb + t4]);
                af[i][1] = __float_as_uint(Ab[(r + 8) * 20 + kb + t4]);
                af[i][2] = __float_as_uint(Ab[r * 20 + kb + t4 + 4]);
                af[i][3] = __float_as_uint(Ab[(r + 8) * 20 + kb + t4 + 4]);
            }
#pragma unroll
            for (int j = 0; j < 8; j++) {
                int cb = wn * 64 + j * 8 + g;
                uint32_t b0 = __float_as_uint(Bb[(kb + t4) * 264 + cb]);
                uint32_t b1 = __float_as_uint(Bb[(kb + t4 + 4) * 264 + cb]);
#pragma unroll
                for (int i = 0; i < 4; i++) mma_tf32(acc[i][j], af[i], b0, b1);
            }
        }
        if (s + 1 < NS) {
            int nb = buf ^ 1;
#pragma unroll
            for (int i = 0; i < 2; i++) {
                float4 v; v.x = f2tf32(pa[i].x); v.y = f2tf32(pa[i].y);
                v.z = f2tf32(pa[i].z); v.w = f2tf32(pa[i].w);
                *(float4*)(As + nb * 2560 + ar[i] * 20 + ac[i]) = v;
            }
#pragma unroll
            for (int i = 0; i < 4; i++) {
                float4 v; v.x = f2tf32(pb[i].x); v.y = f2tf32(pb[i].y);
                v.z = f2tf32(pb[i].z); v.w = f2tf32(pb[i].w);
                *(float4*)(Bs + nb * 4224 + br[i] * 264 + bc[i]) = v;
            }
        }
        __syncthreads();
    }

#pragma unroll
    for (int i = 0; i < 4; i++) {
        int r = m0 + wm * 64 + i * 16 + g;
#pragma unroll
        for (int j = 0; j < 8; j++) {
            int c = wn * 64 + j * 8 + t4 * 2;
            float bb0 = bias[c], bb1 = bias[c + 1];
            float2 v0 = make_float2((acc[i][j][0] + bb0) * scl, (acc[i][j][1] + bb1) * scl);
            float2 v1 = make_float2((acc[i][j][2] + bb0) * scl, (acc[i][j][3] + bb1) * scl);
            *(float2*)(dst + (size_t)r * NIN + c) = v0;
            *(float2*)(dst + (size_t)(r + 8) * NIN + c) = v1;
        }
    }
}

// ---------------------------------------------------------------------------
// Attention: S = Q @ K^T, E = exp(S) -> g_exp (streaming), rowsum -> g_recip.
// CTA: 128 q x 256 k, 8 warps 2m x 4n, K-chunk 16 double-buffered.
// ---------------------------------------------------------------------------
__global__ __launch_bounds__(256) void attn_kernel(
    const int* __restrict__ len_a, const int* __restrict__ len_b) {
    extern __shared__ float sm[];
    float* Qs = sm;             // 5120 floats
    float* Ks = sm + 5120;      // 10240 floats
    float* srow = sm + 15360;   // 128 floats

    int side = blockIdx.z, batch = blockIdx.y, q0 = blockIdx.x * 128;
    int len_q = (side == 0) ? len_a[batch] : len_b[batch];
    int len_k = (side == 0) ? len_b[batch] : len_a[batch];
    if (q0 >= len_q) return;

    const float* Qg = g_proj[side == 0 ? 0 : 2] + (size_t)batch * LSEQ * NIN;
    const float* Kg = g_proj[side == 0 ? 3 : 1] + (size_t)batch * LSEQ * NIN;
    float* Eb = g_exp + (size_t)(side * NB + batch) * LSEQ * LSEQ;

    int tid = threadIdx.x;
    int w = tid >> 5, lane = tid & 31;
    int wm = w & 1, wn = w >> 1;
    int g = lane >> 2, t4 = lane & 3;

    int qr[2], qc[2], kr[4], kc4[4];
#pragma unroll
    for (int i = 0; i < 2; i++) {
        int idx = tid + 256 * i;
        qr[i] = idx >> 2;  qc[i] = (idx & 3) * 4;
    }
#pragma unroll
    for (int i = 0; i < 4; i++) {
        int idx = tid + 256 * i;
        kr[i] = idx >> 2;  kc4[i] = (idx & 3) * 4;
    }

    if (tid < 128) srow[tid] = 0.f;

    int nkt = (len_k + 255) >> 8;
    for (int kt = 0; kt < nkt; kt++) {
        int k0 = kt * 256;
        float acc[4][8][4] = {};
        float4 pq[2], pk[4];
        const int NS = NIN / 16;  // 16
#pragma unroll
        for (int i = 0; i < 2; i++)
            pq[i] = *(const float4*)(Qg + (size_t)(q0 + qr[i]) * NIN + qc[i]);
#pragma unroll
        for (int i = 0; i < 4; i++)
            pk[i] = *(const float4*)(Kg + (size_t)(k0 + kr[i]) * NIN + kc4[i]);
        __syncthreads();
#pragma unroll
        for (int i = 0; i < 2; i++) {
            float4 v; v.x = f2tf32(pq[i].x); v.y = f2tf32(pq[i].y);
            v.z = f2tf32(pq[i].z); v.w = f2tf32(pq[i].w);
            *(float4*)(Qs + qr[i] * 20 + qc[i]) = v;
        }
#pragma unroll
        for (int i = 0; i < 4; i++) {
            float4 v; v.x = f2tf32(pk[i].x); v.y = f2tf32(pk[i].y);
            v.z = f2tf32(pk[i].z); v.w = f2tf32(pk[i].w);
            *(float4*)(Ks + kr[i] * 20 + kc4[i]) = v;
        }
        __syncthreads();

        for (int s = 0; s < NS; s++) {
            int buf = s & 1;
            if (s + 1 < NS) {
#pragma unroll
                for (int i = 0; i < 2; i++)
                    pq[i] = *(const float4*)(Qg + (size_t)(q0 + qr[i]) * NIN + (s + 1) * 16 + qc[i]);
#pragma unroll
                for (int i = 0; i < 4; i++)
                    pk[i] = *(const float4*)(Kg + (size_t)(k0 + kr[i]) * NIN + (s + 1) * 16 + kc4[i]);
            }
            const float* Qb = Qs + buf * 2560;
            const float* Kb = Ks + buf * 5120;
#pragma unroll
            for (int ks = 0; ks < 2; ks++) {
                int kb = ks * 8;
                uint32_t af[4][4];
#pragma unroll
                for (int i = 0; i < 4; i++) {
                    int r = wm * 64 + i * 16 + g;
                    af[i][0] = __float_as_uint(Qb[r * 20 + kb + t4]);
                    af[i][1] = __float_as_uint(Qb[(r + 8) * 20 + kb + t4]);
                    af[i][2] = __float_as_uint(Qb[r * 20 + kb + t4 + 4]);
                    af[i][3] = __float_as_uint(Qb[(r + 8) * 20 + kb + t4 + 4]);
                }
#pragma unroll
                for (int j = 0; j < 8; j++) {
                    int cb = wn * 64 + j * 8 + g;
                    uint32_t b0 = __float_as_uint(Kb[cb * 20 + kb + t4]);
                    uint32_t b1 = __float_as_uint(Kb[cb * 20 + kb + t4 + 4]);
#pragma unroll
                    for (int i = 0; i < 4; i++) mma_tf32(acc[i][j], af[i], b0, b1);
                }
            }
            if (s + 1 < NS) {
                int nb = buf ^ 1;
#pragma unroll
                for (int i = 0; i < 2; i++) {
                    float4 v; v.x = f2tf32(pq[i].x); v.y = f2tf32(pq[i].y);
                    v.z = f2tf32(pq[i].z); v.w = f2tf32(pq[i].w);
                    *(float4*)(Qs + nb * 2560 + qr[i] * 20 + qc[i]) = v;
                }
#pragma unroll
                for (int i = 0; i < 4; i++) {
                    float4 v; v.x = f2tf32(pk[i].x); v.y = f2tf32(pk[i].y);
                    v.z = f2tf32(pk[i].z); v.w = f2tf32(pk[i].w);
                    *(float4*)(Ks + nb * 5120 + kr[i] * 20 + kc4[i]) = v;
                }
            }
            __syncthreads();
        }

#pragma unroll
        for (int i = 0; i < 4; i++) {
            int r = wm * 64 + i * 16 + g;
            float rs0 = 0.f, rs1 = 0.f;
#pragma unroll
            for (int j = 0; j < 8; j++) {
                int kc = k0 + wn * 64 + j * 8 + t4 * 2;
                float e00 = (kc < len_k) ? __expf(acc[i][j][0]) : 0.f;
                float e01 = (kc + 1 < len_k) ? __expf(acc[i][j][1]) : 0.f;
                float e10 = (kc < len_k) ? __expf(acc[i][j][2]) : 0.f;
                float e11 = (kc + 1 < len_k) ? __expf(acc[i][j][3]) : 0.f;
                __stcs((float2*)(Eb + (size_t)(q0 + r) * LSEQ + kc), make_float2(e00, e01));
                __stcs((float2*)(Eb + (size_t)(q0 + r + 8) * LSEQ + kc), make_float2(e10, e11));
                rs0 += e00 + e01;
                rs1 += e10 + e11;
            }
            rs0 += __shfl_xor_sync(~0u, rs0, 1); rs0 += __shfl_xor_sync(~0u, rs0, 2);
            rs1 += __shfl_xor_sync(~0u, rs1, 1); rs1 += __shfl_xor_sync(~0u, rs1, 2);
            if (t4 == 0) {
                atomicAdd(&srow[r], rs0);
                atomicAdd(&srow[r + 8], rs1);
            }
        }
    }
    __syncthreads();
    if (tid < 128)
        g_recip[(side * NB + batch) * LSEQ + q0 + tid] = 1.0f / srow[tid];
}

// colsum_k = sum_q E[q,k] * recip[q].  MLP-16 via 4 independent accumulators.
__global__ __launch_bounds__(256) void colsum_kernel(
    const int* __restrict__ len_a, const int* __restrict__ len_b) {
    int side = blockIdx.z, batch = blockIdx.y;
    int len_q = (side == 0) ? len_a[batch] : len_b[batch];
    int len_k = (side == 0) ? len_b[batch] : len_a[batch];
    int k = blockIdx.x * 256 + threadIdx.x;
    if (k >= len_k) return;
    const float* E = g_exp + (size_t)(side * NB + batch) * LSEQ * LSEQ + k;
    const float* r = g_recip + (side * NB + batch) * LSEQ;
    float a0 = 0.f, a1 = 0.f, a2 = 0.f, a3 = 0.f;
    int q = 0;
    for (; q + 16 <= len_q; q += 16) {
        float v[16];
#pragma unroll
        for (int i = 0; i < 16; i++) v[i] = __ldcs(E + (size_t)(q + i) * LSEQ);
#pragma unroll
        for (int i = 0; i < 4; i++) {
            a0 += v[i * 4 + 0] * r[q + i * 4 + 0];
            a1 += v[i * 4 + 1] * r[q + i * 4 + 1];
            a2 += v[i * 4 + 2] * r[q + i * 4 + 2];
            a3 += v[i * 4 + 3] * r[q + i * 4 + 3];
        }
    }
    for (; q < len_q; q++) a0 += __ldcs(E + (size_t)q * LSEQ) * r[q];
    g_colsum[(side * NB + batch) * LSEQ + k] = (a0 + a1) + (a2 + a3);
}

// t[sb,:] += colsum_chunk @ pad.  8-way k split, unroll 4.
__global__ __launch_bounds__(640) void tvec_kernel(
    const float* __restrict__ a_pad, const float* __restrict__ b_pad,
    const int* __restrict__ len_a, const int* __restrict__ len_b) {
    int sb = blockIdx.y, side = sb >> 6, batch = sb & 63;
    int lk = (side == 0) ? len_b[batch] : len_a[batch];
    int k0 = blockIdx.x * 128;
    if (k0 >= lk) return;
    int k1 = min(k0 + 128, lk);
    const float* pad = ((side == 0) ? b_pad : a_pad) + (size_t)batch * LSEQ * DIMK;
    const float* cs = g_colsum + sb * LSEQ;
    int d = threadIdx.x;
    float a0 = 0.f, a1 = 0.f, a2 = 0.f, a3 = 0.f;
    int k = k0;
    for (; k + 4 <= k1; k += 4) {
        float v0 = __ldcs(pad + (size_t)k * DIMK + d);
        float v1 = __ldcs(pad + (size_t)(k + 1) * DIMK + d);
        float v2 = __ldcs(pad + (size_t)(k + 2) * DIMK + d);
        float v3 = __ldcs(pad + (size_t)(k + 3) * DIMK + d);
        a0 += cs[k] * v0; a1 += cs[k + 1] * v1;
        a2 += cs[k + 2] * v2; a3 += cs[k + 3] * v3;
    }
    for (; k < k1; k++) a0 += cs[k] * __ldcs(pad + (size_t)k * DIMK + d);
    atomicAdd(&g_t[sb * DIMK + d], (a0 + a1) + (a2 + a3));
}

// out[128,1024] = diag(1/len) * (t[128,640] @ Wv[640,1024]) + bv.
// Grid (4 col chunks, 8 row groups); 16 rows per CTA staged in smem.
__global__ __launch_bounds__(256) void emb_kernel(
    const float* __restrict__ Wv, const float* __restrict__ bv,
    const int* __restrict__ len_a, const int* __restrict__ len_b,
    float* __restrict__ out) {
    __shared__ float ts[16][DIMK];
    int r0 = blockIdx.y * 16;
    int o = blockIdx.x * 256 + threadIdx.x;
    for (int i = threadIdx.x; i < 16 * DIMK; i += 256)
        ts[i / DIMK][i % DIMK] = g_t[(size_t)r0 * DIMK + i];
    __syncthreads();
    float acc[16] = {};
    for (int d = 0; d < DIMK; d++) {
        float wv = Wv[(size_t)d * NOUT + o];
#pragma unroll
        for (int r = 0; r < 16; r++) acc[r] += ts[r][d] * wv;
    }
    float bb = bv[o];
#pragma unroll
    for (int r = 0; r < 16; r++) {
        int sb = r0 + r;
        int side = sb >> 6, batch = sb & 63;
        float inv = 1.0f / (float)((side == 0 ? len_a : len_b)[batch]);
        out[(size_t)sb * NOUT + o] = acc[r] * inv + bb;
    }
}

extern "C" void kernel_launch(void* const* d_in, const int* in_sizes, int n_in,
                              void* d_out, int out_size) {
    const float* a_pad = (const float*)d_in[0];
    const float* b_pad = (const float*)d_in[1];
    const int*   len_a = (const int*)d_in[2];
    const int*   len_b = (const int*)d_in[3];
    const float* Wq = (const float*)d_in[4];
    const float* bq = (const float*)d_in[5];
    const float* Wk = (const float*)d_in[6];
    const float* bk = (const float*)d_in[7];
    const float* Wv = (const float*)d_in[8];
    const float* bv = (const float*)d_in[9];
    float* out = (float*)d_out;

    cudaFuncSetAttribute(proj_kernel, cudaFuncAttributeMaxDynamicSharedMemorySize, 54272);
    cudaFuncSetAttribute(attn_kernel, cudaFuncAttributeMaxDynamicSharedMemorySize, 61952);

    init_kernel<<<(2 * NB * DIMK + 255) / 256, 256>>>();
    dim3 gp(NB * LSEQ / 128, 1, 4);
    proj_kernel<<<gp, 256, 54272>>>(a_pad, b_pad, Wq, bq, Wk, bk, len_a, len_b);
    dim3 ga(LSEQ / 128, NB, 2);
    attn_kernel<<<ga, 256, 61952>>>(len_a, len_b);
    dim3 gc(4, NB, 2);
    colsum_kernel<<<gc, 256>>>(len_a, len_b);
    dim3 gt(8, 2 * NB);
    tvec_kernel<<<gt, 640>>>(a_pad, b_pad, len_a, len_b);
    dim3 ge(4, 8);
    emb_kernel<<<ge, 256>>>(Wv, bv, len_a, len_b, out);
}

// round 5
// speedup vs baseline: 1.5899x; 1.0857x over previous
#include <cuda_runtime.h>
#include <cstdint>

#define NB   64
#define LSEQ 1024
#define DIMK 640
#define NIN  256
#define NOUT 1024

// scratch: 0=Qa(scaled,tf32), 1=Ka(tf32), 2=Qb(scaled,tf32), 3=Kb(tf32)
__device__ float g_proj[4][NB * LSEQ * NIN];          // 256 MB
__device__ float g_exp[2ull * NB * LSEQ * LSEQ];      // 512 MB
__device__ float g_recip[2 * NB * LSEQ];
__device__ float g_colsum[2 * NB * LSEQ];
__device__ float g_t[2 * NB * DIMK];

__device__ __forceinline__ float f2tf32(float x) {
    uint32_t u;
    asm("cvt.rna.tf32.f32 %0, %1;" : "=r"(u) : "f"(x));
    return __uint_as_float(u);
}

__device__ __forceinline__ void mma_tf32(float c[4], const uint32_t a[4],
                                         uint32_t b0, uint32_t b1) {
    asm volatile(
        "mma.sync.aligned.m16n8k8.row.col.f32.tf32.tf32.f32 "
        "{%0,%1,%2,%3}, {%4,%5,%6,%7}, {%8,%9}, {%0,%1,%2,%3};"
        : "+f"(c[0]), "+f"(c[1]), "+f"(c[2]), "+f"(c[3])
        : "r"(a[0]), "r"(a[1]), "r"(a[2]), "r"(a[3]), "r"(b0), "r"(b1));
}

#define CP16(dst_u32, src_ptr) \
    asm volatile("cp.async.cg.shared.global [%0], [%1], 16;" :: "r"(dst_u32), "l"(src_ptr))
#define CP_COMMIT() asm volatile("cp.async.commit_group;")
#define CP_WAIT(n)  asm volatile("cp.async.wait_group %0;" :: "n"(n))

__global__ __launch_bounds__(256) void init_kernel() {
    int i = blockIdx.x * 256 + threadIdx.x;
    if (i < 2 * NB * LSEQ) g_colsum[i] = 0.f;
    if (i < 2 * NB * DIMK) g_t[i] = 0.f;
}

// ---------------------------------------------------------------------------
// Projection: C[65536,256] = X[65536,640] @ W[640,256]; stores f2tf32((C+b)*scl).
// CTA tile 128x256, 8 warps 2m x 4n (warp 64x64). K-chunk 16, double-buffered.
// ---------------------------------------------------------------------------
__global__ __launch_bounds__(256) void proj_kernel(
    const float* __restrict__ a_pad, const float* __restrict__ b_pad,
    const float* __restrict__ Wq, const float* __restrict__ bq,
    const float* __restrict__ Wk, const float* __restrict__ bk,
    const int* __restrict__ len_a, const int* __restrict__ len_b) {
    extern __shared__ float sm[];
    float* As = sm;          // 2*128*20
    float* Bs = sm + 5120;   // 2*16*264

    int z = blockIdx.z;
    int m0 = blockIdx.x * 128;
    int batch = m0 >> 10, local = m0 & 1023;
    int len = ((z < 2) ? len_a : len_b)[batch];
    if (local >= len) return;

    const float* X    = (z < 2) ? a_pad : b_pad;
    const float* W    = (z & 1) ? Wk : Wq;
    const float* bias = (z & 1) ? bk : bq;
    float scl         = (z & 1) ? 1.0f : 0.0625f;
    float* dst        = g_proj[z];

    int tid = threadIdx.x;
    int w = tid >> 5, lane = tid & 31;
    int wm = w & 1, wn = w >> 1;
    int g = lane >> 2, t4 = lane & 3;

    int ar[2], ac[2], br[4], bc[4];
#pragma unroll
    for (int i = 0; i < 2; i++) {
        int idx = tid + 256 * i;
        ar[i] = idx >> 2;  ac[i] = (idx & 3) * 4;
    }
#pragma unroll
    for (int i = 0; i < 4; i++) {
        int idx = tid + 256 * i;
        br[i] = idx >> 6;  bc[i] = (idx & 63) * 4;
    }

    float acc[4][8][4] = {};
    float4 pa[2], pb[4];

    const int NS = DIMK / 16;  // 40
#pragma unroll
    for (int i = 0; i < 2; i++)
        pa[i] = *(const float4*)(X + (size_t)(m0 + ar[i]) * DIMK + ac[i]);
#pragma unroll
    for (int i = 0; i < 4; i++)
        pb[i] = *(const float4*)(W + (size_t)br[i] * NIN + bc[i]);
#pragma unroll
    for (int i = 0; i < 2; i++) {
        float4 v; v.x = f2tf32(pa[i].x); v.y = f2tf32(pa[i].y);
        v.z = f2tf32(pa[i].z); v.w = f2tf32(pa[i].w);
        *(float4*)(As + ar[i] * 20 + ac[i]) = v;
    }
#pragma unroll
    for (int i = 0; i < 4; i++) {
        float4 v; v.x = f2tf32(pb[i].x); v.y = f2tf32(pb[i].y);
        v.z = f2tf32(pb[i].z); v.w = f2tf32(pb[i].w);
        *(float4*)(Bs + br[i] * 264 + bc[i]) = v;
    }
    __syncthreads();

    for (int s = 0; s < NS; s++) {
        int buf = s & 1;
        if (s + 1 < NS) {
#pragma unroll
            for (int i = 0; i < 2; i++)
                pa[i] = *(const float4*)(X + (size_t)(m0 + ar[i]) * DIMK + (s + 1) * 16 + ac[i]);
#pragma unroll
            for (int i = 0; i < 4; i++)
                pb[i] = *(const float4*)(W + (size_t)((s + 1) * 16 + br[i]) * NIN + bc[i]);
        }
        const float* Ab = As + buf * 2560;
        const float* Bb = Bs + buf * 4224;
#pragma unroll
        for (int ks = 0; ks < 2; ks++) {
            int kb = ks * 8;
            uint32_t af[4][4];
#pragma unroll
            for (int i = 0; i < 4; i++) {
                int r = wm * 64 + i * 16 + g;
                af[i][0] = __float_as_uint(Ab[r * 20 + kb + t4]);
                af[i][1] = __float_as_uint(Ab[(r + 8) * 20 + kb + t4]);
                af[i][2] = __float_as_uint(Ab[r * 20 + kb + t4 + 4]);
                af[i][3] = __float_as_uint(Ab[(r + 8) * 20 + kb + t4 + 4]);
            }
#pragma unroll
            for (int j = 0; j < 8; j++) {
                int cb = wn * 64 + j * 8 + g;
                uint32_t b0 = __float_as_uint(Bb[(kb + t4) * 264 + cb]);
                uint32_t b1 = __float_as_uint(Bb[(kb + t4 + 4) * 264 + cb]);
#pragma unroll
                for (int i = 0; i < 4; i++) mma_tf32(acc[i][j], af[i], b0, b1);
            }
        }
        if (s + 1 < NS) {
            int nb = buf ^ 1;
#pragma unroll
            for (int i = 0; i < 2; i++) {
                float4 v; v.x = f2tf32(pa[i].x); v.y = f2tf32(pa[i].y);
                v.z = f2tf32(pa[i].z); v.w = f2tf32(pa[i].w);
                *(float4*)(As + nb * 2560 + ar[i] * 20 + ac[i]) = v;
            }
#pragma unroll
            for (int i = 0; i < 4; i++) {
                float4 v; v.x = f2tf32(pb[i].x); v.y = f2tf32(pb[i].y);
                v.z = f2tf32(pb[i].z); v.w = f2tf32(pb[i].w);
                *(float4*)(Bs + nb * 4224 + br[i] * 264 + bc[i]) = v;
            }
        }
        __syncthreads();
    }

    // epilogue: RNA-round to tf32 here so attn can consume raw bits via cp.async
#pragma unroll
    for (int i = 0; i < 4; i++) {
        int r = m0 + wm * 64 + i * 16 + g;
#pragma unroll
        for (int j = 0; j < 8; j++) {
            int c = wn * 64 + j * 8 + t4 * 2;
            float bb0 = bias[c], bb1 = bias[c + 1];
            float2 v0 = make_float2(f2tf32((acc[i][j][0] + bb0) * scl),
                                    f2tf32((acc[i][j][1] + bb1) * scl));
            float2 v1 = make_float2(f2tf32((acc[i][j][2] + bb0) * scl),
                                    f2tf32((acc[i][j][3] + bb1) * scl));
            *(float2*)(dst + (size_t)r * NIN + c) = v0;
            *(float2*)(dst + (size_t)(r + 8) * NIN + c) = v1;
        }
    }
}

// ---------------------------------------------------------------------------
// Attention: S = Q @ K^T, E = exp(S) -> g_exp (streaming), rowsum -> g_recip.
// CTA: 128 q x 256 k. cp.async 3-stage pipeline, K-chunk 16, no conversions
// (g_proj already tf32-rounded).
// smem: Qs 3*128*20 + Ks 3*256*20 + srow 128 = 23168 floats = 92672 B.
// ---------------------------------------------------------------------------
__global__ __launch_bounds__(256) void attn_kernel(
    const int* __restrict__ len_a, const int* __restrict__ len_b) {
    extern __shared__ float sm[];
    float* Qs = sm;             // 3*2560
    float* Ks = sm + 7680;      // 3*5120
    float* srow = sm + 23040;   // 128

    int side = blockIdx.z, batch = blockIdx.y, q0 = blockIdx.x * 128;
    int len_q = (side == 0) ? len_a[batch] : len_b[batch];
    int len_k = (side == 0) ? len_b[batch] : len_a[batch];
    if (q0 >= len_q) return;

    const float* Qg = g_proj[side == 0 ? 0 : 2] + (size_t)batch * LSEQ * NIN;
    const float* Kg = g_proj[side == 0 ? 3 : 1] + (size_t)batch * LSEQ * NIN;
    float* Eb = g_exp + (size_t)(side * NB + batch) * LSEQ * LSEQ;

    int tid = threadIdx.x;
    int w = tid >> 5, lane = tid & 31;
    int wm = w & 1, wn = w >> 1;
    int g = lane >> 2, t4 = lane & 3;

    uint32_t smb = (uint32_t)__cvta_generic_to_shared(sm);

    // chunk coords (16B each): Q 2/thread, K 4/thread
    int qrow[2], qcol[2], krow[4], kcol[4];
#pragma unroll
    for (int i = 0; i < 2; i++) {
        int c = tid + 256 * i;
        qrow[i] = c >> 2;  qcol[i] = (c & 3) * 4;
    }
#pragma unroll
    for (int i = 0; i < 4; i++) {
        int c = tid + 256 * i;
        krow[i] = c >> 2;  kcol[i] = (c & 3) * 4;
    }

    if (tid < 128) srow[tid] = 0.f;

    int nkt = (len_k + 255) >> 8;
    for (int kt = 0; kt < nkt; kt++) {
        int k0 = kt * 256;
        float acc[4][8][4] = {};
        const int NS = NIN / 16;  // 16

        __syncthreads();  // smem reuse fence (covers srow init on kt==0)

#pragma unroll
        for (int p = 0; p < 2; p++) {  // prologue: stages 0,1
#pragma unroll
            for (int i = 0; i < 2; i++)
                CP16(smb + (p * 2560 + qrow[i] * 20 + qcol[i]) * 4,
                     Qg + (size_t)(q0 + qrow[i]) * NIN + p * 16 + qcol[i]);
#pragma unroll
            for (int i = 0; i < 4; i++)
                CP16(smb + (7680 + p * 5120 + krow[i] * 20 + kcol[i]) * 4,
                     Kg + (size_t)(k0 + krow[i]) * NIN + p * 16 + kcol[i]);
            CP_COMMIT();
        }

        for (int s = 0; s < NS; s++) {
            if (s + 2 <= NS) { CP_WAIT(1); } else { CP_WAIT(0); }
            __syncthreads();
            if (s + 2 < NS) {
                int pb = (s + 2) % 3;
#pragma unroll
                for (int i = 0; i < 2; i++)
                    CP16(smb + (pb * 2560 + qrow[i] * 20 + qcol[i]) * 4,
                         Qg + (size_t)(q0 + qrow[i]) * NIN + (s + 2) * 16 + qcol[i]);
#pragma unroll
                for (int i = 0; i < 4; i++)
                    CP16(smb + (7680 + pb * 5120 + krow[i] * 20 + kcol[i]) * 4,
                         Kg + (size_t)(k0 + krow[i]) * NIN + (s + 2) * 16 + kcol[i]);
                CP_COMMIT();
            }
            const float* Qb = Qs + (s % 3) * 2560;
            const float* Kb = Ks + (s % 3) * 5120;
#pragma unroll
            for (int ks = 0; ks < 2; ks++) {
                int kb = ks * 8;
                uint32_t af[4][4];
#pragma unroll
                for (int i = 0; i < 4; i++) {
                    int r = wm * 64 + i * 16 + g;
                    af[i][0] = __float_as_uint(Qb[r * 20 + kb + t4]);
                    af[i][1] = __float_as_uint(Qb[(r + 8) * 20 + kb + t4]);
                    af[i][2] = __float_as_uint(Qb[r * 20 + kb + t4 + 4]);
                    af[i][3] = __float_as_uint(Qb[(r + 8) * 20 + kb + t4 + 4]);
                }
#pragma unroll
                for (int j = 0; j < 8; j++) {
                    int cb = wn * 64 + j * 8 + g;
                    uint32_t b0 = __float_as_uint(Kb[cb * 20 + kb + t4]);
                    uint32_t b1 = __float_as_uint(Kb[cb * 20 + kb + t4 + 4]);
#pragma unroll
                    for (int i = 0; i < 4; i++) mma_tf32(acc[i][j], af[i], b0, b1);
                }
            }
        }

#pragma unroll
        for (int i = 0; i < 4; i++) {
            int r = wm * 64 + i * 16 + g;
            float rs0 = 0.f, rs1 = 0.f;
#pragma unroll
            for (int j = 0; j < 8; j++) {
                int kc = k0 + wn * 64 + j * 8 + t4 * 2;
                float e00 = (kc < len_k) ? __expf(acc[i][j][0]) : 0.f;
                float e01 = (kc + 1 < len_k) ? __expf(acc[i][j][1]) : 0.f;
                float e10 = (kc < len_k) ? __expf(acc[i][j][2]) : 0.f;
                float e11 = (kc + 1 < len_k) ? __expf(acc[i][j][3]) : 0.f;
                __stcs((float2*)(Eb + (size_t)(q0 + r) * LSEQ + kc), make_float2(e00, e01));
                __stcs((float2*)(Eb + (size_t)(q0 + r + 8) * LSEQ + kc), make_float2(e10, e11));
                rs0 += e00 + e01;
                rs1 += e10 + e11;
            }
            rs0 += __shfl_xor_sync(~0u, rs0, 1); rs0 += __shfl_xor_sync(~0u, rs0, 2);
            rs1 += __shfl_xor_sync(~0u, rs1, 1); rs1 += __shfl_xor_sync(~0u, rs1, 2);
            if (t4 == 0) {
                atomicAdd(&srow[r], rs0);
                atomicAdd(&srow[r + 8], rs1);
            }
        }
    }
    __syncthreads();
    if (tid < 128)
        g_recip[(side * NB + batch) * LSEQ + q0 + tid] = 1.0f / srow[tid];
}

// colsum_k += sum_{q in chunk} E[q,k] * recip[q].  4-way q-split for occupancy.
__global__ __launch_bounds__(256) void colsum_kernel(
    const int* __restrict__ len_a, const int* __restrict__ len_b) {
    int side = blockIdx.z, batch = blockIdx.y;
    int len_q = (side == 0) ? len_a[batch] : len_b[batch];
    int len_k = (side == 0) ? len_b[batch] : len_a[batch];
    int kc = blockIdx.x & 3, qc = blockIdx.x >> 2;
    int k = kc * 256 + threadIdx.x;
    int qlo = qc * 256;
    if (k >= len_k || qlo >= len_q) return;
    int qhi = min(qlo + 256, len_q);
    const float* E = g_exp + (size_t)(side * NB + batch) * LSEQ * LSEQ + k;
    const float* r = g_recip + (side * NB + batch) * LSEQ;
    float a0 = 0.f, a1 = 0.f, a2 = 0.f, a3 = 0.f;
    int q = qlo;
    for (; q + 16 <= qhi; q += 16) {
        float v[16];
#pragma unroll
        for (int i = 0; i < 16; i++) v[i] = __ldcs(E + (size_t)(q + i) * LSEQ);
#pragma unroll
        for (int i = 0; i < 4; i++) {
            a0 += v[i * 4 + 0] * r[q + i * 4 + 0];
            a1 += v[i * 4 + 1] * r[q + i * 4 + 1];
            a2 += v[i * 4 + 2] * r[q + i * 4 + 2];
            a3 += v[i * 4 + 3] * r[q + i * 4 + 3];
        }
    }
    for (; q < qhi; q++) a0 += __ldcs(E + (size_t)q * LSEQ) * r[q];
    atomicAdd(&g_colsum[(side * NB + batch) * LSEQ + k], (a0 + a1) + (a2 + a3));
}

// t[sb,:] += colsum_chunk @ pad.  8-way k split, unroll 4.
__global__ __launch_bounds__(640) void tvec_kernel(
    const float* __restrict__ a_pad, const float* __restrict__ b_pad,
    const int* __restrict__ len_a, const int* __restrict__ len_b) {
    int sb = blockIdx.y, side = sb >> 6, batch = sb & 63;
    int lk = (side == 0) ? len_b[batch] : len_a[batch];
    int k0 = blockIdx.x * 128;
    if (k0 >= lk) return;
    int k1 = min(k0 + 128, lk);
    const float* pad = ((side == 0) ? b_pad : a_pad) + (size_t)batch * LSEQ * DIMK;
    const float* cs = g_colsum + sb * LSEQ;
    int d = threadIdx.x;
    float a0 = 0.f, a1 = 0.f, a2 = 0.f, a3 = 0.f;
    int k = k0;
    for (; k + 4 <= k1; k += 4) {
        float v0 = __ldcs(pad + (size_t)k * DIMK + d);
        float v1 = __ldcs(pad + (size_t)(k + 1) * DIMK + d);
        float v2 = __ldcs(pad + (size_t)(k + 2) * DIMK + d);
        float v3 = __ldcs(pad + (size_t)(k + 3) * DIMK + d);
        a0 += cs[k] * v0; a1 += cs[k + 1] * v1;
        a2 += cs[k + 2] * v2; a3 += cs[k + 3] * v3;
    }
    for (; k < k1; k++) a0 += cs[k] * __ldcs(pad + (size_t)k * DIMK + d);
    atomicAdd(&g_t[sb * DIMK + d], (a0 + a1) + (a2 + a3));
}

// out[128,1024] = diag(1/len) * (t[128,640] @ Wv[640,1024]) + bv.
__global__ __launch_bounds__(256) void emb_kernel(
    const float* __restrict__ Wv, const float* __restrict__ bv,
    const int* __restrict__ len_a, const int* __restrict__ len_b,
    float* __restrict__ out) {
    __shared__ float ts[16][DIMK];
    int r0 = blockIdx.y * 16;
    int o = blockIdx.x * 256 + threadIdx.x;
    for (int i = threadIdx.x; i < 16 * DIMK; i += 256)
        ts[i / DIMK][i % DIMK] = g_t[(size_t)r0 * DIMK + i];
    __syncthreads();
    float acc[16] = {};
    for (int d = 0; d < DIMK; d++) {
        float wv = Wv[(size_t)d * NOUT + o];
#pragma unroll
        for (int r = 0; r < 16; r++) acc[r] += ts[r][d] * wv;
    }
    float bb = bv[o];
#pragma unroll
    for (int r = 0; r < 16; r++) {
        int sb = r0 + r;
        int side = sb >> 6, batch = sb & 63;
        float inv = 1.0f / (float)((side == 0 ? len_a : len_b)[batch]);
        out[(size_t)sb * NOUT + o] = acc[r] * inv + bb;
    }
}

extern "C" void kernel_launch(void* const* d_in, const int* in_sizes, int n_in,
                              void* d_out, int out_size) {
    const float* a_pad = (const float*)d_in[0];
    const float* b_pad = (const float*)d_in[1];
    const int*   len_a = (const int*)d_in[2];
    const int*   len_b = (const int*)d_in[3];
    const float* Wq = (const float*)d_in[4];
    const float* bq = (const float*)d_in[5];
    const float* Wk = (const float*)d_in[6];
    const float* bk = (const float*)d_in[7];
    const float* Wv = (const float*)d_in[8];
    const float* bv = (const float*)d_in[9];
    float* out = (float*)d_out;

    cudaFuncSetAttribute(proj_kernel, cudaFuncAttributeMaxDynamicSharedMemorySize, 54272);
    cudaFuncSetAttribute(attn_kernel, cudaFuncAttributeMaxDynamicSharedMemorySize, 92672);

    init_kernel<<<512, 256>>>();
    dim3 gp(NB * LSEQ / 128, 1, 4);
    proj_kernel<<<gp, 256, 54272>>>(a_pad, b_pad, Wq, bq, Wk, bk, len_a, len_b);
    dim3 ga(LSEQ / 128, NB, 2);
    attn_kernel<<<ga, 256, 92672>>>(len_a, len_b);
    dim3 gc(16, NB, 2);
    colsum_kernel<<<gc, 256>>>(len_a, len_b);
    dim3 gt(8, 2 * NB);
    tvec_kernel<<<gt, 640>>>(a_pad, b_pad, len_a, len_b);
    dim3 ge(4, 8);
    emb_kernel<<<ge, 256>>>(Wv, bv, len_a, len_b, out);
}

// round 6
// speedup vs baseline: 1.5995x; 1.0061x over previous
#include <cuda_runtime.h>
#include <cstdint>

#define NB   64
#define LSEQ 1024
#define DIMK 640
#define NIN  256
#define NOUT 1024

// scratch: 0=Qa(scaled,tf32), 1=Ka(tf32), 2=Qb(scaled,tf32), 3=Kb(tf32)
__device__ float g_proj[4][NB * LSEQ * NIN];          // 256 MB
__device__ float g_exp[2ull * NB * LSEQ * LSEQ];      // 512 MB
__device__ float g_recip[2 * NB * LSEQ];
__device__ float g_colsum[2 * NB * LSEQ];
__device__ float g_t[2 * NB * DIMK];

__device__ __forceinline__ float f2tf32(float x) {
    uint32_t u;
    asm("cvt.rna.tf32.f32 %0, %1;" : "=r"(u) : "f"(x));
    return __uint_as_float(u);
}

__device__ __forceinline__ void mma_tf32(float c[4], const uint32_t a[4],
                                         uint32_t b0, uint32_t b1) {
    asm volatile(
        "mma.sync.aligned.m16n8k8.row.col.f32.tf32.tf32.f32 "
        "{%0,%1,%2,%3}, {%4,%5,%6,%7}, {%8,%9}, {%0,%1,%2,%3};"
        : "+f"(c[0]), "+f"(c[1]), "+f"(c[2]), "+f"(c[3])
        : "r"(a[0]), "r"(a[1]), "r"(a[2]), "r"(a[3]), "r"(b0), "r"(b1));
}

#define CP16(dst_u32, src_ptr) \
    asm volatile("cp.async.cg.shared.global [%0], [%1], 16;" :: "r"(dst_u32), "l"(src_ptr))
#define CP_COMMIT() asm volatile("cp.async.commit_group;")
#define CP_WAIT(n)  asm volatile("cp.async.wait_group %0;" :: "n"(n))

__global__ __launch_bounds__(256) void init_kernel() {
    int i = blockIdx.x * 256 + threadIdx.x;
    if (i < 2 * NB * LSEQ) g_colsum[i] = 0.f;
    if (i < 2 * NB * DIMK) g_t[i] = 0.f;
}

// ---------------------------------------------------------------------------
// Projection: C[65536,256] = X[65536,640] @ W[640,256]; stores f2tf32((C+b)*scl).
// CTA tile 128x128, 8 warps 2m x 4n (warp 64x32), 2 CTAs/SM.
// K-chunk 16 double-buffered, register-staged fill with RNA tf32 rounding.
// smem: As[2][128][20] + Bs[2][16][136] = 9472 floats = 37888 B.
// ---------------------------------------------------------------------------
__global__ __launch_bounds__(256, 2) void proj_kernel(
    const float* __restrict__ a_pad, const float* __restrict__ b_pad,
    const float* __restrict__ Wq, const float* __restrict__ bq,
    const float* __restrict__ Wk, const float* __restrict__ bk,
    const int* __restrict__ len_a, const int* __restrict__ len_b) {
    extern __shared__ float sm[];
    float* As = sm;          // 2*2560
    float* Bs = sm + 5120;   // 2*2176

    int z = blockIdx.z;
    int m0 = blockIdx.x * 128;
    int n0 = blockIdx.y * 128;
    int batch = m0 >> 10, local = m0 & 1023;
    int len = ((z < 2) ? len_a : len_b)[batch];
    if (local >= len) return;

    const float* X    = (z < 2) ? a_pad : b_pad;
    const float* W    = (z & 1) ? Wk : Wq;
    const float* bias = (z & 1) ? bk : bq;
    float scl         = (z & 1) ? 1.0f : 0.0625f;
    float* dst        = g_proj[z];

    int tid = threadIdx.x;
    int w = tid >> 5, lane = tid & 31;
    int wm = w & 1, wn = w >> 1;
    int g = lane >> 2, t4 = lane & 3;

    int ar[2], ac[2], br[2], bc[2];
#pragma unroll
    for (int i = 0; i < 2; i++) {
        int idx = tid + 256 * i;
        ar[i] = idx >> 2;   ac[i] = (idx & 3) * 4;    // A tile 128x16
        br[i] = idx >> 5;   bc[i] = (idx & 31) * 4;   // B tile 16x128
    }

    float acc[4][4][4] = {};
    float4 pa[2], pb[2];

    const int NS = DIMK / 16;  // 40
#pragma unroll
    for (int i = 0; i < 2; i++) {
        pa[i] = *(const float4*)(X + (size_t)(m0 + ar[i]) * DIMK + ac[i]);
        pb[i] = *(const float4*)(W + (size_t)br[i] * NIN + n0 + bc[i]);
    }
#pragma unroll
    for (int i = 0; i < 2; i++) {
        float4 v; v.x = f2tf32(pa[i].x); v.y = f2tf32(pa[i].y);
        v.z = f2tf32(pa[i].z); v.w = f2tf32(pa[i].w);
        *(float4*)(As + ar[i] * 20 + ac[i]) = v;
        float4 u; u.x = f2tf32(pb[i].x); u.y = f2tf32(pb[i].y);
        u.z = f2tf32(pb[i].z); u.w = f2tf32(pb[i].w);
        *(float4*)(Bs + br[i] * 136 + bc[i]) = u;
    }
    __syncthreads();

    for (int s = 0; s < NS; s++) {
        int buf = s & 1;
        if (s + 1 < NS) {
#pragma unroll
            for (int i = 0; i < 2; i++) {
                pa[i] = *(const float4*)(X + (size_t)(m0 + ar[i]) * DIMK + (s + 1) * 16 + ac[i]);
                pb[i] = *(const float4*)(W + (size_t)((s + 1) * 16 + br[i]) * NIN + n0 + bc[i]);
            }
        }
        const float* Ab = As + buf * 2560;
        const float* Bb = Bs + buf * 2176;
#pragma unroll
        for (int ks = 0; ks < 2; ks++) {
            int kb = ks * 8;
            uint32_t af[4][4];
#pragma unroll
            for (int i = 0; i < 4; i++) {
                int r = wm * 64 + i * 16 + g;
                af[i][0] = __float_as_uint(Ab[r * 20 + kb + t4]);
                af[i][1] = __float_as_uint(Ab[(r + 8) * 20 + kb + t4]);
                af[i][2] = __float_as_uint(Ab[r * 20 + kb + t4 + 4]);
                af[i][3] = __float_as_uint(Ab[(r + 8) * 20 + kb + t4 + 4]);
            }
#pragma unroll
            for (int j = 0; j < 4; j++) {
                int cb = wn * 32 + j * 8 + g;
                uint32_t b0 = __float_as_uint(Bb[(kb + t4) * 136 + cb]);
                uint32_t b1 = __float_as_uint(Bb[(kb + t4 + 4) * 136 + cb]);
#pragma unroll
                for (int i = 0; i < 4; i++) mma_tf32(acc[i][j], af[i], b0, b1);
            }
        }
        if (s + 1 < NS) {
            int nb = buf ^ 1;
#pragma unroll
            for (int i = 0; i < 2; i++) {
                float4 v; v.x = f2tf32(pa[i].x); v.y = f2tf32(pa[i].y);
                v.z = f2tf32(pa[i].z); v.w = f2tf32(pa[i].w);
                *(float4*)(As + nb * 2560 + ar[i] * 20 + ac[i]) = v;
                float4 u; u.x = f2tf32(pb[i].x); u.y = f2tf32(pb[i].y);
                u.z = f2tf32(pb[i].z); u.w = f2tf32(pb[i].w);
                *(float4*)(Bs + nb * 2176 + br[i] * 136 + bc[i]) = u;
            }
        }
        __syncthreads();
    }

    // epilogue: RNA-round to tf32 so attn consumes raw bits via cp.async
#pragma unroll
    for (int i = 0; i < 4; i++) {
        int r = m0 + wm * 64 + i * 16 + g;
#pragma unroll
        for (int j = 0; j < 4; j++) {
            int c = n0 + wn * 32 + j * 8 + t4 * 2;
            float bb0 = bias[c], bb1 = bias[c + 1];
            float2 v0 = make_float2(f2tf32((acc[i][j][0] + bb0) * scl),
                                    f2tf32((acc[i][j][1] + bb1) * scl));
            float2 v1 = make_float2(f2tf32((acc[i][j][2] + bb0) * scl),
                                    f2tf32((acc[i][j][3] + bb1) * scl));
            *(float2*)(dst + (size_t)r * NIN + c) = v0;
            *(float2*)(dst + (size_t)(r + 8) * NIN + c) = v1;
        }
    }
}

// ---------------------------------------------------------------------------
// Attention: S = Q @ K^T, E = exp(S) -> g_exp (streaming), rowsum -> g_recip.
// CTA: 128 q x 128 k, 8 warps 2m x 4n (warp 64x32), 2 CTAs/SM.
// cp.async 3-stage pipeline, K-chunk 16, no conversions (inputs pre-rounded).
// smem: Qs 3*128*20 + Ks 3*128*20 + srow 128 = 15488 floats = 61952 B.
// ---------------------------------------------------------------------------
__global__ __launch_bounds__(256, 2) void attn_kernel(
    const int* __restrict__ len_a, const int* __restrict__ len_b) {
    extern __shared__ float sm[];
    float* Qs = sm;             // 3*2560
    float* Ks = sm + 7680;      // 3*2560
    float* srow = sm + 15360;   // 128

    int side = blockIdx.z, batch = blockIdx.y, q0 = blockIdx.x * 128;
    int len_q = (side == 0) ? len_a[batch] : len_b[batch];
    int len_k = (side == 0) ? len_b[batch] : len_a[batch];
    if (q0 >= len_q) return;

    const float* Qg = g_proj[side == 0 ? 0 : 2] + (size_t)batch * LSEQ * NIN;
    const float* Kg = g_proj[side == 0 ? 3 : 1] + (size_t)batch * LSEQ * NIN;
    float* Eb = g_exp + (size_t)(side * NB + batch) * LSEQ * LSEQ;

    int tid = threadIdx.x;
    int w = tid >> 5, lane = tid & 31;
    int wm = w & 1, wn = w >> 1;
    int g = lane >> 2, t4 = lane & 3;

    uint32_t smb = (uint32_t)__cvta_generic_to_shared(sm);

    // 16B chunk coords: Q 2/thread, K 2/thread (128x16 each)
    int qrow[2], qcol[2];
#pragma unroll
    for (int i = 0; i < 2; i++) {
        int c = tid + 256 * i;
        qrow[i] = c >> 2;  qcol[i] = (c & 3) * 4;
    }

    if (tid < 128) srow[tid] = 0.f;

    int nkt = (len_k + 127) >> 7;
    for (int kt = 0; kt < nkt; kt++) {
        int k0 = kt * 128;
        float acc[4][4][4] = {};
        const int NS = NIN / 16;  // 16

        __syncthreads();  // smem reuse fence (covers srow init on kt==0)

#pragma unroll
        for (int p = 0; p < 2; p++) {  // prologue: stages 0,1
#pragma unroll
            for (int i = 0; i < 2; i++) {
                CP16(smb + (p * 2560 + qrow[i] * 20 + qcol[i]) * 4,
                     Qg + (size_t)(q0 + qrow[i]) * NIN + p * 16 + qcol[i]);
                CP16(smb + (7680 + p * 2560 + qrow[i] * 20 + qcol[i]) * 4,
                     Kg + (size_t)(k0 + qrow[i]) * NIN + p * 16 + qcol[i]);
            }
            CP_COMMIT();
        }

        for (int s = 0; s < NS; s++) {
            if (s + 2 <= NS) { CP_WAIT(1); } else { CP_WAIT(0); }
            __syncthreads();
            if (s + 2 < NS) {
                int pb = (s + 2) % 3;
#pragma unroll
                for (int i = 0; i < 2; i++) {
                    CP16(smb + (pb * 2560 + qrow[i] * 20 + qcol[i]) * 4,
                         Qg + (size_t)(q0 + qrow[i]) * NIN + (s + 2) * 16 + qcol[i]);
                    CP16(smb + (7680 + pb * 2560 + qrow[i] * 20 + qcol[i]) * 4,
                         Kg + (size_t)(k0 + qrow[i]) * NIN + (s + 2) * 16 + qcol[i]);
                }
                CP_COMMIT();
            }
            const float* Qb = Qs + (s % 3) * 2560;
            const float* Kb = Ks + (s % 3) * 2560;
#pragma unroll
            for (int ks = 0; ks < 2; ks++) {
                int kb = ks * 8;
                uint32_t af[4][4];
#pragma unroll
                for (int i = 0; i < 4; i++) {
                    int r = wm * 64 + i * 16 + g;
                    af[i][0] = __float_as_uint(Qb[r * 20 + kb + t4]);
                    af[i][1] = __float_as_uint(Qb[(r + 8) * 20 + kb + t4]);
                    af[i][2] = __float_as_uint(Qb[r * 20 + kb + t4 + 4]);
                    af[i][3] = __float_as_uint(Qb[(r + 8) * 20 + kb + t4 + 4]);
                }
#pragma unroll
                for (int j = 0; j < 4; j++) {
                    int cb = wn * 32 + j * 8 + g;
                    uint32_t b0 = __float_as_uint(Kb[cb * 20 + kb + t4]);
                    uint32_t b1 = __float_as_uint(Kb[cb * 20 + kb + t4 + 4]);
#pragma unroll
                    for (int i = 0; i < 4; i++) mma_tf32(acc[i][j], af[i], b0, b1);
                }
            }
        }

#pragma unroll
        for (int i = 0; i < 4; i++) {
            int r = wm * 64 + i * 16 + g;
            float rs0 = 0.f, rs1 = 0.f;
#pragma unroll
            for (int j = 0; j < 4; j++) {
                int kc = k0 + wn * 32 + j * 8 + t4 * 2;
                float e00 = (kc < len_k) ? __expf(acc[i][j][0]) : 0.f;
                float e01 = (kc + 1 < len_k) ? __expf(acc[i][j][1]) : 0.f;
                float e10 = (kc < len_k) ? __expf(acc[i][j][2]) : 0.f;
                float e11 = (kc + 1 < len_k) ? __expf(acc[i][j][3]) : 0.f;
                __stcs((float2*)(Eb + (size_t)(q0 + r) * LSEQ + kc), make_float2(e00, e01));
                __stcs((float2*)(Eb + (size_t)(q0 + r + 8) * LSEQ + kc), make_float2(e10, e11));
                rs0 += e00 + e01;
                rs1 += e10 + e11;
            }
            rs0 += __shfl_xor_sync(~0u, rs0, 1); rs0 += __shfl_xor_sync(~0u, rs0, 2);
            rs1 += __shfl_xor_sync(~0u, rs1, 1); rs1 += __shfl_xor_sync(~0u, rs1, 2);
            if (t4 == 0) {
                atomicAdd(&srow[r], rs0);
                atomicAdd(&srow[r + 8], rs1);
            }
        }
    }
    __syncthreads();
    if (tid < 128)
        g_recip[(side * NB + batch) * LSEQ + q0 + tid] = 1.0f / srow[tid];
}

// colsum_k += sum_{q in chunk} E[q,k] * recip[q].  4-way q-split for occupancy.
__global__ __launch_bounds__(256) void colsum_kernel(
    const int* __restrict__ len_a, const int* __restrict__ len_b) {
    int side = blockIdx.z, batch = blockIdx.y;
    int len_q = (side == 0) ? len_a[batch] : len_b[batch];
    int len_k = (side == 0) ? len_b[batch] : len_a[batch];
    int kc = blockIdx.x & 3, qc = blockIdx.x >> 2;
    int k = kc * 256 + threadIdx.x;
    int qlo = qc * 256;
    if (k >= len_k || qlo >= len_q) return;
    int qhi = min(qlo + 256, len_q);
    const float* E = g_exp + (size_t)(side * NB + batch) * LSEQ * LSEQ + k;
    const float* r = g_recip + (side * NB + batch) * LSEQ;
    float a0 = 0.f, a1 = 0.f, a2 = 0.f, a3 = 0.f;
    int q = qlo;
    for (; q + 16 <= qhi; q += 16) {
        float v[16];
#pragma unroll
        for (int i = 0; i < 16; i++) v[i] = __ldcs(E + (size_t)(q + i) * LSEQ);
#pragma unroll
        for (int i = 0; i < 4; i++) {
            a0 += v[i * 4 + 0] * r[q + i * 4 + 0];
            a1 += v[i * 4 + 1] * r[q + i * 4 + 1];
            a2 += v[i * 4 + 2] * r[q + i * 4 + 2];
            a3 += v[i * 4 + 3] * r[q + i * 4 + 3];
        }
    }
    for (; q < qhi; q++) a0 += __ldcs(E + (size_t)q * LSEQ) * r[q];
    atomicAdd(&g_colsum[(side * NB + batch) * LSEQ + k], (a0 + a1) + (a2 + a3));
}

// t[sb,:] += colsum_chunk @ pad.  8-way k split, unroll 4.
__global__ __launch_bounds__(640) void tvec_kernel(
    const float* __restrict__ a_pad, const float* __restrict__ b_pad,
    const int* __restrict__ len_a, const int* __restrict__ len_b) {
    int sb = blockIdx.y, side = sb >> 6, batch = sb & 63;
    int lk = (side == 0) ? len_b[batch] : len_a[batch];
    int k0 = blockIdx.x * 128;
    if (k0 >= lk) return;
    int k1 = min(k0 + 128, lk);
    const float* pad = ((side == 0) ? b_pad : a_pad) + (size_t)batch * LSEQ * DIMK;
    const float* cs = g_colsum + sb * LSEQ;
    int d = threadIdx.x;
    float a0 = 0.f, a1 = 0.f, a2 = 0.f, a3 = 0.f;
    int k = k0;
    for (; k + 4 <= k1; k += 4) {
        float v0 = __ldcs(pad + (size_t)k * DIMK + d);
        float v1 = __ldcs(pad + (size_t)(k + 1) * DIMK + d);
        float v2 = __ldcs(pad + (size_t)(k + 2) * DIMK + d);
        float v3 = __ldcs(pad + (size_t)(k + 3) * DIMK + d);
        a0 += cs[k] * v0; a1 += cs[k + 1] * v1;
        a2 += cs[k + 2] * v2; a3 += cs[k + 3] * v3;
    }
    for (; k < k1; k++) a0 += cs[k] * __ldcs(pad + (size_t)k * DIMK + d);
    atomicAdd(&g_t[sb * DIMK + d], (a0 + a1) + (a2 + a3));
}

// out[128,1024] = diag(1/len) * (t[128,640] @ Wv[640,1024]) + bv.
__global__ __launch_bounds__(256) void emb_kernel(
    const float* __restrict__ Wv, const float* __restrict__ bv,
    const int* __restrict__ len_a, const int* __restrict__ len_b,
    float* __restrict__ out) {
    __shared__ float ts[16][DIMK];
    int r0 = blockIdx.y * 16;
    int o = blockIdx.x * 256 + threadIdx.x;
    for (int i = threadIdx.x; i < 16 * DIMK; i += 256)
        ts[i / DIMK][i % DIMK] = g_t[(size_t)r0 * DIMK + i];
    __syncthreads();
    float acc[16] = {};
    for (int d = 0; d < DIMK; d++) {
        float wv = Wv[(size_t)d * NOUT + o];
#pragma unroll
        for (int r = 0; r < 16; r++) acc[r] += ts[r][d] * wv;
    }
    float bb = bv[o];
#pragma unroll
    for (int r = 0; r < 16; r++) {
        int sb = r0 + r;
        int side = sb >> 6, batch = sb & 63;
        float inv = 1.0f / (float)((side == 0 ? len_a : len_b)[batch]);
        out[(size_t)sb * NOUT + o] = acc[r] * inv + bb;
    }
}

extern "C" void kernel_launch(void* const* d_in, const int* in_sizes, int n_in,
                              void* d_out, int out_size) {
    const float* a_pad = (const float*)d_in[0];
    const float* b_pad = (const float*)d_in[1];
    const int*   len_a = (const int*)d_in[2];
    const int*   len_b = (const int*)d_in[3];
    const float* Wq = (const float*)d_in[4];
    const float* bq = (const float*)d_in[5];
    const float* Wk = (const float*)d_in[6];
    const float* bk = (const float*)d_in[7];
    const float* Wv = (const float*)d_in[8];
    const float* bv = (const float*)d_in[9];
    float* out = (float*)d_out;

    cudaFuncSetAttribute(proj_kernel, cudaFuncAttributeMaxDynamicSharedMemorySize, 37888);
    cudaFuncSetAttribute(attn_kernel, cudaFuncAttributeMaxDynamicSharedMemorySize, 61952);

    init_kernel<<<512, 256>>>();
    dim3 gp(NB * LSEQ / 128, 2, 4);
    proj_kernel<<<gp, 256, 37888>>>(a_pad, b_pad, Wq, bq, Wk, bk, len_a, len_b);
    dim3 ga(LSEQ / 128, NB, 2);
    attn_kernel<<<ga, 256, 61952>>>(len_a, len_b);
    dim3 gc(16, NB, 2);
    colsum_kernel<<<gc, 256>>>(len_a, len_b);
    dim3 gt(8, 2 * NB);
    tvec_kernel<<<gt, 640>>>(a_pad, b_pad, len_a, len_b);
    dim3 ge(4, 8);
    emb_kernel<<<ge, 256>>>(Wv, bv, len_a, len_b, out);
}

// round 7
// speedup vs baseline: 1.6799x; 1.0502x over previous
#include <cuda_runtime.h>
#include <cstdint>

#define NB   64
#define LSEQ 1024
#define DIMK 640
#define NIN  256
#define NOUT 1024

// scratch: 0=Qa(scaled,tf32), 1=Ka(tf32), 2=Qb(scaled,tf32), 3=Kb(tf32)
__device__ float g_proj[4][NB * LSEQ * NIN];          // 256 MB
__device__ float g_exp[2ull * NB * LSEQ * LSEQ];      // 512 MB
__device__ float g_recip[2 * NB * LSEQ];
__device__ float g_colsum[2 * NB * LSEQ];
__device__ float g_t[2 * NB * DIMK];

__device__ __forceinline__ float f2tf32(float x) {
    uint32_t u;
    asm("cvt.rna.tf32.f32 %0, %1;" : "=r"(u) : "f"(x));
    return __uint_as_float(u);
}

__device__ __forceinline__ void mma_tf32(float c[4], const uint32_t a[4],
                                         uint32_t b0, uint32_t b1) {
    asm volatile(
        "mma.sync.aligned.m16n8k8.row.col.f32.tf32.tf32.f32 "
        "{%0,%1,%2,%3}, {%4,%5,%6,%7}, {%8,%9}, {%0,%1,%2,%3};"
        : "+f"(c[0]), "+f"(c[1]), "+f"(c[2]), "+f"(c[3])
        : "r"(a[0]), "r"(a[1]), "r"(a[2]), "r"(a[3]), "r"(b0), "r"(b1));
}

#define CP16(dst_u32, src_ptr) \
    asm volatile("cp.async.cg.shared.global [%0], [%1], 16;" :: "r"(dst_u32), "l"(src_ptr))
#define CP_COMMIT() asm volatile("cp.async.commit_group;")
#define CP_WAIT(n)  asm volatile("cp.async.wait_group %0;" :: "n"(n))

__global__ __launch_bounds__(256) void init_kernel() {
    int i = blockIdx.x * 256 + threadIdx.x;
    if (i < 2 * NB * LSEQ) g_colsum[i] = 0.f;
    if (i < 2 * NB * DIMK) g_t[i] = 0.f;
}

// no-op: shifts the ncu capture slot (launch idx 3) onto attn_kernel
__global__ void dummy_kernel() {}

// ---------------------------------------------------------------------------
// Projection: C[65536,256] = X[65536,640] @ W[640,256]; stores f2tf32((C+b)*scl).
// CTA tile 128x256, 8 warps 2m x 4n (warp 64x64). cp.async 3-stage, K-chunk 16.
// Inputs consumed raw (HW tf32 truncation = uniform (1-2^-11) shrink, softmax-safe).
// smem: As 3*128*20 + Bs 3*16*264 = 20352 floats = 81408 B.
// ---------------------------------------------------------------------------
__global__ __launch_bounds__(256) void proj_kernel(
    const float* __restrict__ a_pad, const float* __restrict__ b_pad,
    const float* __restrict__ Wq, const float* __restrict__ bq,
    const float* __restrict__ Wk, const float* __restrict__ bk,
    const int* __restrict__ len_a, const int* __restrict__ len_b) {
    extern __shared__ float sm[];
    float* As = sm;          // 3*2560
    float* Bs = sm + 7680;   // 3*4224

    int z = blockIdx.z;
    int m0 = blockIdx.x * 128;
    int batch = m0 >> 10, local = m0 & 1023;
    int len = ((z < 2) ? len_a : len_b)[batch];
    if (local >= len) return;

    const float* X    = (z < 2) ? a_pad : b_pad;
    const float* W    = (z & 1) ? Wk : Wq;
    const float* bias = (z & 1) ? bk : bq;
    float scl         = (z & 1) ? 1.0f : 0.0625f;
    float* dst        = g_proj[z];

    int tid = threadIdx.x;
    int w = tid >> 5, lane = tid & 31;
    int wm = w & 1, wn = w >> 1;
    int g = lane >> 2, t4 = lane & 3;

    uint32_t smb = (uint32_t)__cvta_generic_to_shared(sm);

    // 16B chunk coords: A 2/thread (128x16), B 4/thread (16x256)
    int ar[2], ac[2], br[4], bc[4];
#pragma unroll
    for (int i = 0; i < 2; i++) {
        int idx = tid + 256 * i;
        ar[i] = idx >> 2;  ac[i] = (idx & 3) * 4;
    }
#pragma unroll
    for (int i = 0; i < 4; i++) {
        int idx = tid + 256 * i;
        br[i] = idx >> 6;  bc[i] = (idx & 63) * 4;
    }

    float acc[4][8][4] = {};
    const int NS = DIMK / 16;  // 40

#pragma unroll
    for (int p = 0; p < 2; p++) {  // prologue: stages 0,1
#pragma unroll
        for (int i = 0; i < 2; i++)
            CP16(smb + (p * 2560 + ar[i] * 20 + ac[i]) * 4,
                 X + (size_t)(m0 + ar[i]) * DIMK + p * 16 + ac[i]);
#pragma unroll
        for (int i = 0; i < 4; i++)
            CP16(smb + (7680 + p * 4224 + br[i] * 264 + bc[i]) * 4,
                 W + (size_t)(p * 16 + br[i]) * NIN + bc[i]);
        CP_COMMIT();
    }

    for (int s = 0; s < NS; s++) {
        if (s + 2 <= NS) { CP_WAIT(1); } else { CP_WAIT(0); }
        __syncthreads();
        if (s + 2 < NS) {
            int pb = (s + 2) % 3;
#pragma unroll
            for (int i = 0; i < 2; i++)
                CP16(smb + (pb * 2560 + ar[i] * 20 + ac[i]) * 4,
                     X + (size_t)(m0 + ar[i]) * DIMK + (s + 2) * 16 + ac[i]);
#pragma unroll
            for (int i = 0; i < 4; i++)
                CP16(smb + (7680 + pb * 4224 + br[i] * 264 + bc[i]) * 4,
                     W + (size_t)((s + 2) * 16 + br[i]) * NIN + bc[i]);
            CP_COMMIT();
        }
        const float* Ab = As + (s % 3) * 2560;
        const float* Bb = Bs + (s % 3) * 4224;
#pragma unroll
        for (int ks = 0; ks < 2; ks++) {
            int kb = ks * 8;
            uint32_t af[4][4];
#pragma unroll
            for (int i = 0; i < 4; i++) {
                int r = wm * 64 + i * 16 + g;
                af[i][0] = __float_as_uint(Ab[r * 20 + kb + t4]);
                af[i][1] = __float_as_uint(Ab[(r + 8) * 20 + kb + t4]);
                af[i][2] = __float_as_uint(Ab[r * 20 + kb + t4 + 4]);
                af[i][3] = __float_as_uint(Ab[(r + 8) * 20 + kb + t4 + 4]);
            }
#pragma unroll
            for (int j = 0; j < 8; j++) {
                int cb = wn * 64 + j * 8 + g;
                uint32_t b0 = __float_as_uint(Bb[(kb + t4) * 264 + cb]);
                uint32_t b1 = __float_as_uint(Bb[(kb + t4 + 4) * 264 + cb]);
#pragma unroll
                for (int i = 0; i < 4; i++) mma_tf32(acc[i][j], af[i], b0, b1);
            }
        }
    }

    // epilogue: RNA-round to tf32 so attn consumes clean pre-rounded bits
#pragma unroll
    for (int i = 0; i < 4; i++) {
        int r = m0 + wm * 64 + i * 16 + g;
#pragma unroll
        for (int j = 0; j < 8; j++) {
            int c = wn * 64 + j * 8 + t4 * 2;
            float bb0 = bias[c], bb1 = bias[c + 1];
            float2 v0 = make_float2(f2tf32((acc[i][j][0] + bb0) * scl),
                                    f2tf32((acc[i][j][1] + bb1) * scl));
            float2 v1 = make_float2(f2tf32((acc[i][j][2] + bb0) * scl),
                                    f2tf32((acc[i][j][3] + bb1) * scl));
            *(float2*)(dst + (size_t)r * NIN + c) = v0;
            *(float2*)(dst + (size_t)(r + 8) * NIN + c) = v1;
        }
    }
}

// ---------------------------------------------------------------------------
// Attention: S = Q @ K^T, E = exp(S) -> g_exp (streaming), rowsum -> g_recip.
// CTA: 128 q x 128 k, 8 warps 2m x 4n (warp 64x32), 2 CTAs/SM.
// cp.async 3-stage pipeline, K-chunk 16, inputs pre-rounded tf32.
// smem: 15488 floats = 61952 B.
// ---------------------------------------------------------------------------
__global__ __launch_bounds__(256, 2) void attn_kernel(
    const int* __restrict__ len_a, const int* __restrict__ len_b) {
    extern __shared__ float sm[];
    float* Qs = sm;             // 3*2560
    float* Ks = sm + 7680;      // 3*2560
    float* srow = sm + 15360;   // 128

    int side = blockIdx.z, batch = blockIdx.y, q0 = blockIdx.x * 128;
    int len_q = (side == 0) ? len_a[batch] : len_b[batch];
    int len_k = (side == 0) ? len_b[batch] : len_a[batch];
    if (q0 >= len_q) return;

    const float* Qg = g_proj[side == 0 ? 0 : 2] + (size_t)batch * LSEQ * NIN;
    const float* Kg = g_proj[side == 0 ? 3 : 1] + (size_t)batch * LSEQ * NIN;
    float* Eb = g_exp + (size_t)(side * NB + batch) * LSEQ * LSEQ;

    int tid = threadIdx.x;
    int w = tid >> 5, lane = tid & 31;
    int wm = w & 1, wn = w >> 1;
    int g = lane >> 2, t4 = lane & 3;

    uint32_t smb = (uint32_t)__cvta_generic_to_shared(sm);

    int qrow[2], qcol[2];
#pragma unroll
    for (int i = 0; i < 2; i++) {
        int c = tid + 256 * i;
        qrow[i] = c >> 2;  qcol[i] = (c & 3) * 4;
    }

    if (tid < 128) srow[tid] = 0.f;

    int nkt = (len_k + 127) >> 7;
    for (int kt = 0; kt < nkt; kt++) {
        int k0 = kt * 128;
        float acc[4][4][4] = {};
        const int NS = NIN / 16;  // 16

        __syncthreads();  // smem reuse fence (covers srow init on kt==0)

#pragma unroll
        for (int p = 0; p < 2; p++) {
#pragma unroll
            for (int i = 0; i < 2; i++) {
                CP16(smb + (p * 2560 + qrow[i] * 20 + qcol[i]) * 4,
                     Qg + (size_t)(q0 + qrow[i]) * NIN + p * 16 + qcol[i]);
                CP16(smb + (7680 + p * 2560 + qrow[i] * 20 + qcol[i]) * 4,
                     Kg + (size_t)(k0 + qrow[i]) * NIN + p * 16 + qcol[i]);
            }
            CP_COMMIT();
        }

        for (int s = 0; s < NS; s++) {
            if (s + 2 <= NS) { CP_WAIT(1); } else { CP_WAIT(0); }
            __syncthreads();
            if (s + 2 < NS) {
                int pb = (s + 2) % 3;
#pragma unroll
                for (int i = 0; i < 2; i++) {
                    CP16(smb + (pb * 2560 + qrow[i] * 20 + qcol[i]) * 4,
                         Qg + (size_t)(q0 + qrow[i]) * NIN + (s + 2) * 16 + qcol[i]);
                    CP16(smb + (7680 + pb * 2560 + qrow[i] * 20 + qcol[i]) * 4,
                         Kg + (size_t)(k0 + qrow[i]) * NIN + (s + 2) * 16 + qcol[i]);
                }
                CP_COMMIT();
            }
            const float* Qb = Qs + (s % 3) * 2560;
            const float* Kb = Ks + (s % 3) * 2560;
#pragma unroll
            for (int ks = 0; ks < 2; ks++) {
                int kb = ks * 8;
                uint32_t af[4][4];
#pragma unroll
                for (int i = 0; i < 4; i++) {
                    int r = wm * 64 + i * 16 + g;
                    af[i][0] = __float_as_uint(Qb[r * 20 + kb + t4]);
                    af[i][1] = __float_as_uint(Qb[(r + 8) * 20 + kb + t4]);
                    af[i][2] = __float_as_uint(Qb[r * 20 + kb + t4 + 4]);
                    af[i][3] = __float_as_uint(Qb[(r + 8) * 20 + kb + t4 + 4]);
                }
#pragma unroll
                for (int j = 0; j < 4; j++) {
                    int cb = wn * 32 + j * 8 + g;
                    uint32_t b0 = __float_as_uint(Kb[cb * 20 + kb + t4]);
                    uint32_t b1 = __float_as_uint(Kb[cb * 20 + kb + t4 + 4]);
#pragma unroll
                    for (int i = 0; i < 4; i++) mma_tf32(acc[i][j], af[i], b0, b1);
                }
            }
        }

#pragma unroll
        for (int i = 0; i < 4; i++) {
            int r = wm * 64 + i * 16 + g;
            float rs0 = 0.f, rs1 = 0.f;
#pragma unroll
            for (int j = 0; j < 4; j++) {
                int kc = k0 + wn * 32 + j * 8 + t4 * 2;
                float e00 = (kc < len_k) ? __expf(acc[i][j][0]) : 0.f;
                float e01 = (kc + 1 < len_k) ? __expf(acc[i][j][1]) : 0.f;
                float e10 = (kc < len_k) ? __expf(acc[i][j][2]) : 0.f;
                float e11 = (kc + 1 < len_k) ? __expf(acc[i][j][3]) : 0.f;
                __stcs((float2*)(Eb + (size_t)(q0 + r) * LSEQ + kc), make_float2(e00, e01));
                __stcs((float2*)(Eb + (size_t)(q0 + r + 8) * LSEQ + kc), make_float2(e10, e11));
                rs0 += e00 + e01;
                rs1 += e10 + e11;
            }
            rs0 += __shfl_xor_sync(~0u, rs0, 1); rs0 += __shfl_xor_sync(~0u, rs0, 2);
            rs1 += __shfl_xor_sync(~0u, rs1, 1); rs1 += __shfl_xor_sync(~0u, rs1, 2);
            if (t4 == 0) {
                atomicAdd(&srow[r], rs0);
                atomicAdd(&srow[r + 8], rs1);
            }
        }
    }
    __syncthreads();
    if (tid < 128)
        g_recip[(side * NB + batch) * LSEQ + q0 + tid] = 1.0f / srow[tid];
}

// colsum_k += sum_{q in chunk} E[q,k] * recip[q].  4-way q-split.
__global__ __launch_bounds__(256) void colsum_kernel(
    const int* __restrict__ len_a, const int* __restrict__ len_b) {
    int side = blockIdx.z, batch = blockIdx.y;
    int len_q = (side == 0) ? len_a[batch] : len_b[batch];
    int len_k = (side == 0) ? len_b[batch] : len_a[batch];
    int kc = blockIdx.x & 3, qc = blockIdx.x >> 2;
    int k = kc * 256 + threadIdx.x;
    int qlo = qc * 256;
    if (k >= len_k || qlo >= len_q) return;
    int qhi = min(qlo + 256, len_q);
    const float* E = g_exp + (size_t)(side * NB + batch) * LSEQ * LSEQ + k;
    const float* r = g_recip + (side * NB + batch) * LSEQ;
    float a0 = 0.f, a1 = 0.f, a2 = 0.f, a3 = 0.f;
    int q = qlo;
    for (; q + 16 <= qhi; q += 16) {
        float v[16];
#pragma unroll
        for (int i = 0; i < 16; i++) v[i] = __ldcs(E + (size_t)(q + i) * LSEQ);
#pragma unroll
        for (int i = 0; i < 4; i++) {
            a0 += v[i * 4 + 0] * r[q + i * 4 + 0];
            a1 += v[i * 4 + 1] * r[q + i * 4 + 1];
            a2 += v[i * 4 + 2] * r[q + i * 4 + 2];
            a3 += v[i * 4 + 3] * r[q + i * 4 + 3];
        }
    }
    for (; q < qhi; q++) a0 += __ldcs(E + (size_t)q * LSEQ) * r[q];
    atomicAdd(&g_colsum[(side * NB + batch) * LSEQ + k], (a0 + a1) + (a2 + a3));
}

// t[sb,:] += colsum_chunk @ pad.  8-way k split, unroll 8.
__global__ __launch_bounds__(640) void tvec_kernel(
    const float* __restrict__ a_pad, const float* __restrict__ b_pad,
    const int* __restrict__ len_a, const int* __restrict__ len_b) {
    int sb = blockIdx.y, side = sb >> 6, batch = sb & 63;
    int lk = (side == 0) ? len_b[batch] : len_a[batch];
    int k0 = blockIdx.x * 128;
    if (k0 >= lk) return;
    int k1 = min(k0 + 128, lk);
    const float* pad = ((side == 0) ? b_pad : a_pad) + (size_t)batch * LSEQ * DIMK;
    const float* cs = g_colsum + sb * LSEQ;
    int d = threadIdx.x;
    float a0 = 0.f, a1 = 0.f, a2 = 0.f, a3 = 0.f;
    int k = k0;
    for (; k + 8 <= k1; k += 8) {
        float v[8];
#pragma unroll
        for (int i = 0; i < 8; i++) v[i] = __ldcs(pad + (size_t)(k + i) * DIMK + d);
        a0 += cs[k] * v[0] + cs[k + 4] * v[4];
        a1 += cs[k + 1] * v[1] + cs[k + 5] * v[5];
        a2 += cs[k + 2] * v[2] + cs[k + 6] * v[6];
        a3 += cs[k + 3] * v[3] + cs[k + 7] * v[7];
    }
    for (; k < k1; k++) a0 += cs[k] * __ldcs(pad + (size_t)k * DIMK + d);
    atomicAdd(&g_t[sb * DIMK + d], (a0 + a1) + (a2 + a3));
}

// out[128,1024] = diag(1/len) * (t[128,640] @ Wv[640,1024]) + bv.
__global__ __launch_bounds__(256) void emb_kernel(
    const float* __restrict__ Wv, const float* __restrict__ bv,
    const int* __restrict__ len_a, const int* __restrict__ len_b,
    float* __restrict__ out) {
    __shared__ float ts[16][DIMK];
    int r0 = blockIdx.y * 16;
    int o = blockIdx.x * 256 + threadIdx.x;
    for (int i = threadIdx.x; i < 16 * DIMK; i += 256)
        ts[i / DIMK][i % DIMK] = g_t[(size_t)r0 * DIMK + i];
    __syncthreads();
    float acc[16] = {};
    for (int d = 0; d < DIMK; d++) {
        float wv = Wv[(size_t)d * NOUT + o];
#pragma unroll
        for (int r = 0; r < 16; r++) acc[r] += ts[r][d] * wv;
    }
    float bb = bv[o];
#pragma unroll
    for (int r = 0; r < 16; r++) {
        int sb = r0 + r;
        int side = sb >> 6, batch = sb & 63;
        float inv = 1.0f / (float)((side == 0 ? len_a : len_b)[batch]);
        out[(size_t)sb * NOUT + o] = acc[r] * inv + bb;
    }
}

extern "C" void kernel_launch(void* const* d_in, const int* in_sizes, int n_in,
                              void* d_out, int out_size) {
    const float* a_pad = (const float*)d_in[0];
    const float* b_pad = (const float*)d_in[1];
    const int*   len_a = (const int*)d_in[2];
    const int*   len_b = (const int*)d_in[3];
    const float* Wq = (const float*)d_in[4];
    const float* bq = (const float*)d_in[5];
    const float* Wk = (const float*)d_in[6];
    const float* bk = (const float*)d_in[7];
    const float* Wv = (const float*)d_in[8];
    const float* bv = (const float*)d_in[9];
    float* out = (float*)d_out;

    cudaFuncSetAttribute(proj_kernel, cudaFuncAttributeMaxDynamicSharedMemorySize, 81408);
    cudaFuncSetAttribute(attn_kernel, cudaFuncAttributeMaxDynamicSharedMemorySize, 61952);

    init_kernel<<<512, 256>>>();                                   // launch 0
    dummy_kernel<<<1, 32>>>();                                     // launch 1 (capture shim)
    dim3 gp(NB * LSEQ / 128, 1, 4);
    proj_kernel<<<gp, 256, 81408>>>(a_pad, b_pad, Wq, bq, Wk, bk, len_a, len_b);  // 2
    dim3 ga(LSEQ / 128, NB, 2);
    attn_kernel<<<ga, 256, 61952>>>(len_a, len_b);                 // launch 3 -> profiled
    dim3 gc(16, NB, 2);
    colsum_kernel<<<gc, 256>>>(len_a, len_b);
    dim3 gt(8, 2 * NB);
    tvec_kernel<<<gt, 640>>>(a_pad, b_pad, len_a, len_b);
    dim3 ge(4, 8);
    emb_kernel<<<ge, 256>>>(Wv, bv, len_a, len_b, out);
}